// round 1
// baseline (speedup 1.0000x reference)
#include <cuda_runtime.h>

#define BATCH 128
#define CDIM 512
#define SDIM 128
#define MDIM 512

// ---------------- scratch (static device globals; no allocation) ----------------
__device__ float g_q[BATCH * CDIM * MDIM];     // 134 MB
__device__ float g_k[BATCH * CDIM * MDIM];     // 134 MB
__device__ float g_vwf[BATCH * CDIM * SDIM];   // 33.5 MB  (value @ Weff^T + beff)
__device__ float g_weff[SDIM * SDIM];
__device__ float g_beff[SDIM];
__device__ float g_psum[CDIM * BATCH];
__device__ float g_psumsq[CDIM * BATCH];
__device__ float g_scale[CDIM];
__device__ float g_shift[CDIM];

// ---------------- K0: Weff = Wf @ Wv  [S,S];  beff = Wf @ bv + bf ----------------
__global__ void weff_kernel(const float* __restrict__ Wf, const float* __restrict__ Wv,
                            const float* __restrict__ bv, const float* __restrict__ bf) {
    int row = blockIdx.x;   // s  (0..127)
    int col = threadIdx.x;  // s' (0..127)
    float acc = 0.f;
    for (int m = 0; m < MDIM; m++)
        acc += Wf[row * MDIM + m] * Wv[m * SDIM + col];
    g_weff[row * SDIM + col] = acc;
    if (col == 0) {
        float b = bf[row];
        for (int m = 0; m < MDIM; m++)
            b += Wf[row * MDIM + m] * bv[m];
        g_beff[row] = b;
    }
}

// ---------------- K1: NT projection GEMM ----------------
// out[row, n] = sum_k X[row,k] * W[n,k] + bias[n];  K = 128 (=S), rows = B*C
// outSel: 0 -> g_q, 1 -> g_k, 2 -> g_vwf (W==nullptr means use g_weff/g_beff)
__global__ __launch_bounds__(256) void proj_kernel(const float* __restrict__ X,
                                                   const float* __restrict__ W,
                                                   const float* __restrict__ bias,
                                                   int ncols, int outSel) {
    __shared__ float Xs[32][132];   // [k][row]
    __shared__ float Ws[32][132];   // [k][n]
    float* out = (outSel == 0) ? g_q : ((outSel == 1) ? g_k : g_vwf);
    if (W == nullptr) { W = g_weff; bias = g_beff; }

    int tx = threadIdx.x, ty = threadIdx.y;
    int tid = ty * 16 + tx;
    int row0 = blockIdx.y * 128;
    int n0 = blockIdx.x * 128;

    float acc[8][8];
    #pragma unroll
    for (int i = 0; i < 8; i++)
        #pragma unroll
        for (int j = 0; j < 8; j++) acc[i][j] = 0.f;

    for (int kc = 0; kc < 4; kc++) {
        __syncthreads();
        #pragma unroll
        for (int t = 0; t < 4; t++) {
            int f = tid + t * 256;       // 0..1023
            int r = f >> 3;              // 0..127
            int k0 = (f & 7) * 4;        // 0..28
            float4 v = *(const float4*)(X + (size_t)(row0 + r) * SDIM + kc * 32 + k0);
            Xs[k0 + 0][r] = v.x; Xs[k0 + 1][r] = v.y; Xs[k0 + 2][r] = v.z; Xs[k0 + 3][r] = v.w;
            float4 w = *(const float4*)(W + (size_t)(n0 + r) * SDIM + kc * 32 + k0);
            Ws[k0 + 0][r] = w.x; Ws[k0 + 1][r] = w.y; Ws[k0 + 2][r] = w.z; Ws[k0 + 3][r] = w.w;
        }
        __syncthreads();
        #pragma unroll
        for (int k = 0; k < 32; k++) {
            float a[8], bb[8];
            *(float4*)(a)     = *(const float4*)&Xs[k][ty * 8];
            *(float4*)(a + 4) = *(const float4*)&Xs[k][ty * 8 + 4];
            *(float4*)(bb)     = *(const float4*)&Ws[k][tx * 8];
            *(float4*)(bb + 4) = *(const float4*)&Ws[k][tx * 8 + 4];
            #pragma unroll
            for (int i = 0; i < 8; i++)
                #pragma unroll
                for (int j = 0; j < 8; j++) acc[i][j] += a[i] * bb[j];
        }
    }

    float bvv[8];
    #pragma unroll
    for (int j = 0; j < 8; j++) bvv[j] = bias[n0 + tx * 8 + j];
    #pragma unroll
    for (int i = 0; i < 8; i++) {
        int row = row0 + ty * 8 + i;
        float4 o0, o1;
        o0.x = acc[i][0] + bvv[0]; o0.y = acc[i][1] + bvv[1];
        o0.z = acc[i][2] + bvv[2]; o0.w = acc[i][3] + bvv[3];
        o1.x = acc[i][4] + bvv[4]; o1.y = acc[i][5] + bvv[5];
        o1.z = acc[i][6] + bvv[6]; o1.w = acc[i][7] + bvv[7];
        *(float4*)(out + (size_t)row * ncols + n0 + tx * 8)     = o0;
        *(float4*)(out + (size_t)row * ncols + n0 + tx * 8 + 4) = o1;
    }
}

// ---------------- K2: scores GEMM + fused row softmax -> attention (d_out) ----------------
// block: 512 threads; covers 64 rows x all 512 cols of one batch; K = M = 512
__global__ __launch_bounds__(512) void attn_kernel(float* __restrict__ att) {
    __shared__ float Qs[16][68];    // [k][row]
    __shared__ float Ks[16][516];   // [k][col]
    __shared__ float red[16][8];

    int b = blockIdx.y;
    int row0 = blockIdx.x * 64;
    int tid = threadIdx.x;
    int tx = tid & 63;   // col group (8 cols each)
    int ty = tid >> 6;   // row group (8 rows each)

    const float* qb = g_q + (size_t)b * CDIM * MDIM + (size_t)row0 * MDIM;
    const float* kb = g_k + (size_t)b * CDIM * MDIM;

    float acc[8][8];
    #pragma unroll
    for (int i = 0; i < 8; i++)
        #pragma unroll
        for (int j = 0; j < 8; j++) acc[i][j] = 0.f;

    for (int kc = 0; kc < 32; kc++) {
        __syncthreads();
        if (tid < 256) {
            int r = tid >> 2, k0 = (tid & 3) * 4;
            float4 v = *(const float4*)(qb + (size_t)r * MDIM + kc * 16 + k0);
            Qs[k0 + 0][r] = v.x; Qs[k0 + 1][r] = v.y; Qs[k0 + 2][r] = v.z; Qs[k0 + 3][r] = v.w;
        }
        #pragma unroll
        for (int t = 0; t < 4; t++) {
            int f = tid + t * 512;       // 0..2047
            int r = f >> 2;              // 0..511
            int k0 = (f & 3) * 4;
            float4 v = *(const float4*)(kb + (size_t)r * MDIM + kc * 16 + k0);
            Ks[k0 + 0][r] = v.x; Ks[k0 + 1][r] = v.y; Ks[k0 + 2][r] = v.z; Ks[k0 + 3][r] = v.w;
        }
        __syncthreads();
        #pragma unroll
        for (int k = 0; k < 16; k++) {
            float a[8], bb[8];
            *(float4*)(a)     = *(const float4*)&Qs[k][ty * 8];
            *(float4*)(a + 4) = *(const float4*)&Qs[k][ty * 8 + 4];
            *(float4*)(bb)     = *(const float4*)&Ks[k][tx * 8];
            *(float4*)(bb + 4) = *(const float4*)&Ks[k][tx * 8 + 4];
            #pragma unroll
            for (int i = 0; i < 8; i++)
                #pragma unroll
                for (int j = 0; j < 8; j++) acc[i][j] += a[i] * bb[j];
        }
    }

    const float SC = 0.04419417382415922f;   // 512^-0.5
    #pragma unroll
    for (int i = 0; i < 8; i++)
        #pragma unroll
        for (int j = 0; j < 8; j++) acc[i][j] *= SC;

    int w = tid >> 5, lane = tid & 31;

    // row max over 64 threads (2 warps) sharing ty
    float mx[8];
    #pragma unroll
    for (int i = 0; i < 8; i++) {
        float m = acc[i][0];
        #pragma unroll
        for (int j = 1; j < 8; j++) m = fmaxf(m, acc[i][j]);
        mx[i] = m;
    }
    #pragma unroll
    for (int off = 16; off; off >>= 1)
        #pragma unroll
        for (int i = 0; i < 8; i++)
            mx[i] = fmaxf(mx[i], __shfl_xor_sync(0xffffffffu, mx[i], off));
    if (lane == 0) {
        #pragma unroll
        for (int i = 0; i < 8; i++) red[w][i] = mx[i];
    }
    __syncthreads();
    #pragma unroll
    for (int i = 0; i < 8; i++) mx[i] = fmaxf(red[ty * 2][i], red[ty * 2 + 1][i]);
    __syncthreads();

    // exp + row sum
    float sm[8];
    #pragma unroll
    for (int i = 0; i < 8; i++) {
        float s = 0.f;
        #pragma unroll
        for (int j = 0; j < 8; j++) {
            float e = __expf(acc[i][j] - mx[i]);
            acc[i][j] = e;
            s += e;
        }
        sm[i] = s;
    }
    #pragma unroll
    for (int off = 16; off; off >>= 1)
        #pragma unroll
        for (int i = 0; i < 8; i++)
            sm[i] += __shfl_xor_sync(0xffffffffu, sm[i], off);
    if (lane == 0) {
        #pragma unroll
        for (int i = 0; i < 8; i++) red[w][i] = sm[i];
    }
    __syncthreads();
    #pragma unroll
    for (int i = 0; i < 8; i++) sm[i] = red[ty * 2][i] + red[ty * 2 + 1][i];

    float* ap = att + (size_t)b * CDIM * CDIM + (size_t)row0 * CDIM;
    #pragma unroll
    for (int i = 0; i < 8; i++) {
        float inv = 1.0f / sm[i];
        int r = ty * 8 + i;
        float4 o0, o1;
        o0.x = acc[i][0] * inv; o0.y = acc[i][1] * inv;
        o0.z = acc[i][2] * inv; o0.w = acc[i][3] * inv;
        o1.x = acc[i][4] * inv; o1.y = acc[i][5] * inv;
        o1.z = acc[i][6] * inv; o1.w = acc[i][7] * inv;
        *(float4*)(ap + (size_t)r * CDIM + tx * 8)     = o0;
        *(float4*)(ap + (size_t)r * CDIM + tx * 8 + 4) = o1;
    }
}

// ---------------- K3: context NN GEMM + BN partial sums ----------------
// outp[b,c,s] = sum_j A[b,c,j] * vwf[b,j,s];  K=512, N=128
__global__ __launch_bounds__(256) void ctx_kernel(const float* __restrict__ att,
                                                  float* __restrict__ outp) {
    __shared__ float As[32][132];   // [j_local][row]
    __shared__ float Bs[32][132];   // [j_local][s]

    int b = blockIdx.y;
    int row0 = blockIdx.x * 128;
    int tx = threadIdx.x, ty = threadIdx.y;
    int tid = ty * 16 + tx;

    const float* ab = att + (size_t)b * CDIM * CDIM + (size_t)row0 * CDIM;
    const float* vb = g_vwf + (size_t)b * CDIM * SDIM;

    float acc[8][8];
    #pragma unroll
    for (int i = 0; i < 8; i++)
        #pragma unroll
        for (int j = 0; j < 8; j++) acc[i][j] = 0.f;

    for (int kc = 0; kc < 16; kc++) {
        __syncthreads();
        #pragma unroll
        for (int t = 0; t < 4; t++) {
            int f = tid + t * 256;       // 0..1023
            int r = f >> 3;              // 0..127
            int k0 = (f & 7) * 4;
            float4 v = *(const float4*)(ab + (size_t)r * CDIM + kc * 32 + k0);
            As[k0 + 0][r] = v.x; As[k0 + 1][r] = v.y; As[k0 + 2][r] = v.z; As[k0 + 3][r] = v.w;
            int jj = f >> 5;             // 0..31
            int s0 = (f & 31) * 4;       // 0..124
            float4 u = *(const float4*)(vb + (size_t)(kc * 32 + jj) * SDIM + s0);
            *(float4*)&Bs[jj][s0] = u;
        }
        __syncthreads();
        #pragma unroll
        for (int k = 0; k < 32; k++) {
            float a[8], bb[8];
            *(float4*)(a)     = *(const float4*)&As[k][ty * 8];
            *(float4*)(a + 4) = *(const float4*)&As[k][ty * 8 + 4];
            *(float4*)(bb)     = *(const float4*)&Bs[k][tx * 8];
            *(float4*)(bb + 4) = *(const float4*)&Bs[k][tx * 8 + 4];
            #pragma unroll
            for (int i = 0; i < 8; i++)
                #pragma unroll
                for (int j = 0; j < 8; j++) acc[i][j] += a[i] * bb[j];
        }
    }

    // write pre-BN output
    #pragma unroll
    for (int i = 0; i < 8; i++) {
        int r = row0 + ty * 8 + i;
        float* p = outp + (size_t)b * CDIM * SDIM + (size_t)r * SDIM + tx * 8;
        float4 o0, o1;
        o0.x = acc[i][0]; o0.y = acc[i][1]; o0.z = acc[i][2]; o0.w = acc[i][3];
        o1.x = acc[i][4]; o1.y = acc[i][5]; o1.z = acc[i][6]; o1.w = acc[i][7];
        *(float4*)(p)     = o0;
        *(float4*)(p + 4) = o1;
    }

    // deterministic BN partials: this block owns (batch b, channels row0..row0+127, all s)
    #pragma unroll
    for (int i = 0; i < 8; i++) {
        float s1 = 0.f, s2 = 0.f;
        #pragma unroll
        for (int j = 0; j < 8; j++) { float v = acc[i][j]; s1 += v; s2 += v * v; }
        #pragma unroll
        for (int off = 8; off; off >>= 1) {
            s1 += __shfl_xor_sync(0xffffffffu, s1, off);
            s2 += __shfl_xor_sync(0xffffffffu, s2, off);
        }
        if (tx == 0) {
            int c = row0 + ty * 8 + i;
            g_psum[(size_t)c * BATCH + b] = s1;
            g_psumsq[(size_t)c * BATCH + b] = s2;
        }
    }
}

// ---------------- K4: finalize BN stats ----------------
__global__ void stats_kernel(const float* __restrict__ gamma, const float* __restrict__ beta) {
    int c = threadIdx.x;
    float s = 0.f, ss = 0.f;
    for (int b = 0; b < BATCH; b++) {
        s += g_psum[(size_t)c * BATCH + b];
        ss += g_psumsq[(size_t)c * BATCH + b];
    }
    const float inv_n = 1.0f / (float)(BATCH * SDIM);
    float mean = s * inv_n;
    float var = ss * inv_n - mean * mean;
    float sc = gamma[c] * rsqrtf(var + 1e-5f);
    g_scale[c] = sc;
    g_shift[c] = beta[c] - mean * sc;
}

// ---------------- K5: apply BN + relu + residual (in place on d_out out-region) ----------------
__global__ void apply_kernel(const float* __restrict__ value, float* __restrict__ out) {
    int idx = blockIdx.x * 256 + threadIdx.x;        // float4 index, 2,097,152 total
    int c = (idx >> 5) & (CDIM - 1);                 // S/4 = 32 float4 per (b,c) row
    float sc = g_scale[c], sh = g_shift[c];
    float4 o = ((const float4*)out)[idx];
    float4 v = ((const float4*)value)[idx];
    o.x = fmaxf(o.x * sc + sh, 0.f) + v.x;
    o.y = fmaxf(o.y * sc + sh, 0.f) + v.y;
    o.z = fmaxf(o.z * sc + sh, 0.f) + v.z;
    o.w = fmaxf(o.w * sc + sh, 0.f) + v.w;
    ((float4*)out)[idx] = o;
}

// ---------------- launch ----------------
extern "C" void kernel_launch(void* const* d_in, const int* in_sizes, int n_in,
                              void* d_out, int out_size) {
    const float* query = (const float*)d_in[0];
    const float* key   = (const float*)d_in[1];
    const float* value = (const float*)d_in[2];
    const float* Wq = (const float*)d_in[3];
    const float* bq = (const float*)d_in[4];
    const float* Wk = (const float*)d_in[5];
    const float* bk = (const float*)d_in[6];
    const float* Wv = (const float*)d_in[7];
    const float* bv = (const float*)d_in[8];
    const float* Wf = (const float*)d_in[9];
    const float* bf = (const float*)d_in[10];
    const float* gamma = (const float*)d_in[11];
    const float* beta  = (const float*)d_in[12];

    float* out = (float*)d_out;                               // [B,C,S]
    float* att = out + (size_t)BATCH * CDIM * SDIM;           // [B,C,C]

    dim3 blk(16, 16);
    weff_kernel<<<SDIM, SDIM>>>(Wf, Wv, bv, bf);
    proj_kernel<<<dim3(4, 512), blk>>>(query, Wq, bq, MDIM, 0);
    proj_kernel<<<dim3(4, 512), blk>>>(key, Wk, bk, MDIM, 1);
    proj_kernel<<<dim3(1, 512), blk>>>(value, nullptr, nullptr, SDIM, 2);
    attn_kernel<<<dim3(8, BATCH), 512>>>(att);
    ctx_kernel<<<dim3(4, BATCH), blk>>>(att, out);
    stats_kernel<<<1, CDIM>>>(gamma, beta);
    apply_kernel<<<8192, 256>>>(value, out);
}

// round 2
// speedup vs baseline: 1.9777x; 1.9777x over previous
#include <cuda_runtime.h>

#define BATCH 128
#define CDIM 512
#define SDIM 128
#define MDIM 512

// ---------------- scratch (static device globals; no allocation) ----------------
__device__ float g_xg[BATCH * CDIM * SDIM];    // 33.5 MB  (Gt-projected query, bias w folded)
__device__ float g_vwf[BATCH * CDIM * SDIM];   // 33.5 MB  (value @ Weff^T + beff)
__device__ float g_gt[SDIM * SDIM];            // Gt[s'][s] = SC * sum_m Wq[m,s] Wk[m,s']
__device__ float g_w[SDIM];                    // SC * Wk^T bq
__device__ float g_weff[SDIM * SDIM];          // Weff[s_out][s_in] = sum_m Wf[s_out,m] Wv[m,s_in]
__device__ float g_beff[SDIM];                 // Wf bv + bf
__device__ float g_psum[CDIM * BATCH];
__device__ float g_psumsq[CDIM * BATCH];
__device__ float g_scale[CDIM];
__device__ float g_shift[CDIM];

// ---------------- K0: prep small matrices ----------------
// block n (0..127), thread k (0..127)
__global__ void prep_kernel(const float* __restrict__ Wq, const float* __restrict__ bq,
                            const float* __restrict__ Wk, const float* __restrict__ bk,
                            const float* __restrict__ Wv, const float* __restrict__ bv,
                            const float* __restrict__ Wf, const float* __restrict__ bf) {
    const float SC = 0.04419417382415922f;   // 512^-0.5
    int n = blockIdx.x;    // s' for Gt, s_out for Weff
    int k = threadIdx.x;   // s  for Gt, s_in  for Weff
    float g = 0.f, e = 0.f;
    for (int m = 0; m < MDIM; m++) {
        g += Wq[m * SDIM + k] * Wk[m * SDIM + n];
        e += Wf[n * MDIM + m] * Wv[m * SDIM + k];
    }
    g_gt[n * SDIM + k] = g * SC;
    g_weff[n * SDIM + k] = e;
    if (k == 0) {
        float w = 0.f, b = bf[n];
        for (int m = 0; m < MDIM; m++) {
            w += Wk[m * SDIM + n] * bq[m];
            b += Wf[n * MDIM + m] * bv[m];
        }
        g_w[n] = w * SC;
        g_beff[n] = b;
    }
}

// ---------------- K1: NT projection GEMM (128-wide output) ----------------
// out[row, n] = sum_k X[row,k] * W[n,k] + bias[n];  K = S = 128, ncols = 128
// sel: 0 -> g_xg (W=g_gt, bias=g_w), 1 -> g_vwf (W=g_weff, bias=g_beff)
__global__ __launch_bounds__(256) void proj_kernel(const float* __restrict__ X, int sel) {
    __shared__ float Xs[32][132];   // [k][row]
    __shared__ float Ws[32][132];   // [k][n]
    float* out = (sel == 0) ? g_xg : g_vwf;
    const float* W = (sel == 0) ? g_gt : g_weff;
    const float* bias = (sel == 0) ? g_w : g_beff;

    int tx = threadIdx.x, ty = threadIdx.y;
    int tid = ty * 16 + tx;
    int row0 = blockIdx.y * 128;

    float acc[8][8];
    #pragma unroll
    for (int i = 0; i < 8; i++)
        #pragma unroll
        for (int j = 0; j < 8; j++) acc[i][j] = 0.f;

    for (int kc = 0; kc < 4; kc++) {
        __syncthreads();
        #pragma unroll
        for (int t = 0; t < 4; t++) {
            int f = tid + t * 256;       // 0..1023
            int r = f >> 3;              // 0..127
            int k0 = (f & 7) * 4;        // 0..28
            float4 v = *(const float4*)(X + (size_t)(row0 + r) * SDIM + kc * 32 + k0);
            Xs[k0 + 0][r] = v.x; Xs[k0 + 1][r] = v.y; Xs[k0 + 2][r] = v.z; Xs[k0 + 3][r] = v.w;
            float4 w = *(const float4*)(W + (size_t)r * SDIM + kc * 32 + k0);
            Ws[k0 + 0][r] = w.x; Ws[k0 + 1][r] = w.y; Ws[k0 + 2][r] = w.z; Ws[k0 + 3][r] = w.w;
        }
        __syncthreads();
        #pragma unroll
        for (int k = 0; k < 32; k++) {
            float a[8], bb[8];
            *(float4*)(a)     = *(const float4*)&Xs[k][ty * 8];
            *(float4*)(a + 4) = *(const float4*)&Xs[k][ty * 8 + 4];
            *(float4*)(bb)     = *(const float4*)&Ws[k][tx * 8];
            *(float4*)(bb + 4) = *(const float4*)&Ws[k][tx * 8 + 4];
            #pragma unroll
            for (int i = 0; i < 8; i++)
                #pragma unroll
                for (int j = 0; j < 8; j++) acc[i][j] += a[i] * bb[j];
        }
    }

    float bvv[8];
    #pragma unroll
    for (int j = 0; j < 8; j++) bvv[j] = bias[tx * 8 + j];
    #pragma unroll
    for (int i = 0; i < 8; i++) {
        int row = row0 + ty * 8 + i;
        float4 o0, o1;
        o0.x = acc[i][0] + bvv[0]; o0.y = acc[i][1] + bvv[1];
        o0.z = acc[i][2] + bvv[2]; o0.w = acc[i][3] + bvv[3];
        o1.x = acc[i][4] + bvv[4]; o1.y = acc[i][5] + bvv[5];
        o1.z = acc[i][6] + bvv[6]; o1.w = acc[i][7] + bvv[7];
        *(float4*)(out + (size_t)row * SDIM + tx * 8)     = o0;
        *(float4*)(out + (size_t)row * SDIM + tx * 8 + 4) = o1;
    }
}

// ---------------- K2: scores NT GEMM (per batch), raw logits -> att ----------------
// att[b,i,j] = sum_k Xg[b,i,k] * key[b,j,k];  K = 128
__global__ __launch_bounds__(256) void scores_kernel(const float* __restrict__ key,
                                                     float* __restrict__ att) {
    __shared__ float Xs[32][132];
    __shared__ float Ks[32][132];

    int b = blockIdx.z;
    int row0 = blockIdx.y * 128;
    int n0 = blockIdx.x * 128;
    int tx = threadIdx.x, ty = threadIdx.y;
    int tid = ty * 16 + tx;

    const float* xb = g_xg + (size_t)b * CDIM * SDIM + (size_t)row0 * SDIM;
    const float* kb = key + (size_t)b * CDIM * SDIM + (size_t)n0 * SDIM;

    float acc[8][8];
    #pragma unroll
    for (int i = 0; i < 8; i++)
        #pragma unroll
        for (int j = 0; j < 8; j++) acc[i][j] = 0.f;

    for (int kc = 0; kc < 4; kc++) {
        __syncthreads();
        #pragma unroll
        for (int t = 0; t < 4; t++) {
            int f = tid + t * 256;
            int r = f >> 3;
            int k0 = (f & 7) * 4;
            float4 v = *(const float4*)(xb + (size_t)r * SDIM + kc * 32 + k0);
            Xs[k0 + 0][r] = v.x; Xs[k0 + 1][r] = v.y; Xs[k0 + 2][r] = v.z; Xs[k0 + 3][r] = v.w;
            float4 w = *(const float4*)(kb + (size_t)r * SDIM + kc * 32 + k0);
            Ks[k0 + 0][r] = w.x; Ks[k0 + 1][r] = w.y; Ks[k0 + 2][r] = w.z; Ks[k0 + 3][r] = w.w;
        }
        __syncthreads();
        #pragma unroll
        for (int k = 0; k < 32; k++) {
            float a[8], bb[8];
            *(float4*)(a)     = *(const float4*)&Xs[k][ty * 8];
            *(float4*)(a + 4) = *(const float4*)&Xs[k][ty * 8 + 4];
            *(float4*)(bb)     = *(const float4*)&Ks[k][tx * 8];
            *(float4*)(bb + 4) = *(const float4*)&Ks[k][tx * 8 + 4];
            #pragma unroll
            for (int i = 0; i < 8; i++)
                #pragma unroll
                for (int j = 0; j < 8; j++) acc[i][j] += a[i] * bb[j];
        }
    }

    float* ap = att + (size_t)b * CDIM * CDIM + (size_t)row0 * CDIM + n0;
    #pragma unroll
    for (int i = 0; i < 8; i++) {
        int r = ty * 8 + i;
        float4 o0, o1;
        o0.x = acc[i][0]; o0.y = acc[i][1]; o0.z = acc[i][2]; o0.w = acc[i][3];
        o1.x = acc[i][4]; o1.y = acc[i][5]; o1.z = acc[i][6]; o1.w = acc[i][7];
        *(float4*)(ap + (size_t)r * CDIM + tx * 8)     = o0;
        *(float4*)(ap + (size_t)r * CDIM + tx * 8 + 4) = o1;
    }
}

// ---------------- K3: warp-per-row softmax, in place ----------------
__global__ __launch_bounds__(256) void softmax_kernel(float* __restrict__ att) {
    size_t row = ((size_t)blockIdx.x * 256 + threadIdx.x) >> 5;
    int lane = threadIdx.x & 31;
    float4* rp = (float4*)(att + row * CDIM);

    float4 v[4];
    #pragma unroll
    for (int i = 0; i < 4; i++) v[i] = rp[lane + i * 32];

    float m = -3.4e38f;
    #pragma unroll
    for (int i = 0; i < 4; i++) {
        m = fmaxf(m, fmaxf(fmaxf(v[i].x, v[i].y), fmaxf(v[i].z, v[i].w)));
    }
    #pragma unroll
    for (int off = 16; off; off >>= 1) m = fmaxf(m, __shfl_xor_sync(0xffffffffu, m, off));

    float s = 0.f;
    #pragma unroll
    for (int i = 0; i < 4; i++) {
        v[i].x = __expf(v[i].x - m); s += v[i].x;
        v[i].y = __expf(v[i].y - m); s += v[i].y;
        v[i].z = __expf(v[i].z - m); s += v[i].z;
        v[i].w = __expf(v[i].w - m); s += v[i].w;
    }
    #pragma unroll
    for (int off = 16; off; off >>= 1) s += __shfl_xor_sync(0xffffffffu, s, off);

    float inv = 1.0f / s;
    #pragma unroll
    for (int i = 0; i < 4; i++) {
        v[i].x *= inv; v[i].y *= inv; v[i].z *= inv; v[i].w *= inv;
        rp[lane + i * 32] = v[i];
    }
}

// ---------------- K4: context NN GEMM + BN partial sums ----------------
// outp[b,c,s] = sum_j A[b,c,j] * vwf[b,j,s];  K=512, N=128
__global__ __launch_bounds__(256) void ctx_kernel(const float* __restrict__ att,
                                                  float* __restrict__ outp) {
    __shared__ float As[32][132];   // [j_local][row]
    __shared__ float Bs[32][132];   // [j_local][s]

    int b = blockIdx.y;
    int row0 = blockIdx.x * 128;
    int tx = threadIdx.x, ty = threadIdx.y;
    int tid = ty * 16 + tx;

    const float* ab = att + (size_t)b * CDIM * CDIM + (size_t)row0 * CDIM;
    const float* vb = g_vwf + (size_t)b * CDIM * SDIM;

    float acc[8][8];
    #pragma unroll
    for (int i = 0; i < 8; i++)
        #pragma unroll
        for (int j = 0; j < 8; j++) acc[i][j] = 0.f;

    for (int kc = 0; kc < 16; kc++) {
        __syncthreads();
        #pragma unroll
        for (int t = 0; t < 4; t++) {
            int f = tid + t * 256;       // 0..1023
            int r = f >> 3;              // 0..127
            int k0 = (f & 7) * 4;
            float4 v = *(const float4*)(ab + (size_t)r * CDIM + kc * 32 + k0);
            As[k0 + 0][r] = v.x; As[k0 + 1][r] = v.y; As[k0 + 2][r] = v.z; As[k0 + 3][r] = v.w;
            int jj = f >> 5;             // 0..31
            int s0 = (f & 31) * 4;       // 0..124
            float4 u = *(const float4*)(vb + (size_t)(kc * 32 + jj) * SDIM + s0);
            *(float4*)&Bs[jj][s0] = u;
        }
        __syncthreads();
        #pragma unroll
        for (int k = 0; k < 32; k++) {
            float a[8], bb[8];
            *(float4*)(a)     = *(const float4*)&As[k][ty * 8];
            *(float4*)(a + 4) = *(const float4*)&As[k][ty * 8 + 4];
            *(float4*)(bb)     = *(const float4*)&Bs[k][tx * 8];
            *(float4*)(bb + 4) = *(const float4*)&Bs[k][tx * 8 + 4];
            #pragma unroll
            for (int i = 0; i < 8; i++)
                #pragma unroll
                for (int j = 0; j < 8; j++) acc[i][j] += a[i] * bb[j];
        }
    }

    // write pre-BN output
    #pragma unroll
    for (int i = 0; i < 8; i++) {
        int r = row0 + ty * 8 + i;
        float* p = outp + (size_t)b * CDIM * SDIM + (size_t)r * SDIM + tx * 8;
        float4 o0, o1;
        o0.x = acc[i][0]; o0.y = acc[i][1]; o0.z = acc[i][2]; o0.w = acc[i][3];
        o1.x = acc[i][4]; o1.y = acc[i][5]; o1.z = acc[i][6]; o1.w = acc[i][7];
        *(float4*)(p)     = o0;
        *(float4*)(p + 4) = o1;
    }

    // deterministic BN partials: this block owns (batch b, channels row0..row0+127, all s)
    #pragma unroll
    for (int i = 0; i < 8; i++) {
        float s1 = 0.f, s2 = 0.f;
        #pragma unroll
        for (int j = 0; j < 8; j++) { float v = acc[i][j]; s1 += v; s2 += v * v; }
        #pragma unroll
        for (int off = 8; off; off >>= 1) {
            s1 += __shfl_xor_sync(0xffffffffu, s1, off);
            s2 += __shfl_xor_sync(0xffffffffu, s2, off);
        }
        if (tx == 0) {
            int c = row0 + ty * 8 + i;
            g_psum[(size_t)c * BATCH + b] = s1;
            g_psumsq[(size_t)c * BATCH + b] = s2;
        }
    }
}

// ---------------- K5: finalize BN stats ----------------
__global__ void stats_kernel(const float* __restrict__ gamma, const float* __restrict__ beta) {
    int c = threadIdx.x;
    float s = 0.f, ss = 0.f;
    for (int b = 0; b < BATCH; b++) {
        s += g_psum[(size_t)c * BATCH + b];
        ss += g_psumsq[(size_t)c * BATCH + b];
    }
    const float inv_n = 1.0f / (float)(BATCH * SDIM);
    float mean = s * inv_n;
    float var = ss * inv_n - mean * mean;
    float sc = gamma[c] * rsqrtf(var + 1e-5f);
    g_scale[c] = sc;
    g_shift[c] = beta[c] - mean * sc;
}

// ---------------- K6: apply BN + relu + residual ----------------
__global__ void apply_kernel(const float* __restrict__ value, float* __restrict__ out) {
    int idx = blockIdx.x * 256 + threadIdx.x;        // float4 index
    int c = (idx >> 5) & (CDIM - 1);                 // 32 float4 per (b,c) row
    float sc = g_scale[c], sh = g_shift[c];
    float4 o = ((const float4*)out)[idx];
    float4 v = ((const float4*)value)[idx];
    o.x = fmaxf(o.x * sc + sh, 0.f) + v.x;
    o.y = fmaxf(o.y * sc + sh, 0.f) + v.y;
    o.z = fmaxf(o.z * sc + sh, 0.f) + v.z;
    o.w = fmaxf(o.w * sc + sh, 0.f) + v.w;
    ((float4*)out)[idx] = o;
}

// ---------------- launch ----------------
extern "C" void kernel_launch(void* const* d_in, const int* in_sizes, int n_in,
                              void* d_out, int out_size) {
    const float* query = (const float*)d_in[0];
    const float* key   = (const float*)d_in[1];
    const float* value = (const float*)d_in[2];
    const float* Wq = (const float*)d_in[3];
    const float* bq = (const float*)d_in[4];
    const float* Wk = (const float*)d_in[5];
    const float* bk = (const float*)d_in[6];
    const float* Wv = (const float*)d_in[7];
    const float* bv = (const float*)d_in[8];
    const float* Wf = (const float*)d_in[9];
    const float* bf = (const float*)d_in[10];
    const float* gamma = (const float*)d_in[11];
    const float* beta  = (const float*)d_in[12];

    float* out = (float*)d_out;                               // [B,C,S]
    float* att = out + (size_t)BATCH * CDIM * SDIM;           // [B,C,C]

    dim3 blk(16, 16);
    prep_kernel<<<SDIM, SDIM>>>(Wq, bq, Wk, bk, Wv, bv, Wf, bf);
    proj_kernel<<<dim3(1, 512), blk>>>(query, 0);
    proj_kernel<<<dim3(1, 512), blk>>>(value, 1);
    scores_kernel<<<dim3(4, 4, BATCH), blk>>>(key, att);
    softmax_kernel<<<8192, 256>>>(att);
    ctx_kernel<<<dim3(4, BATCH), blk>>>(att, out);
    stats_kernel<<<1, CDIM>>>(gamma, beta);
    apply_kernel<<<8192, 256>>>(value, out);
}

// round 3
// speedup vs baseline: 2.0860x; 1.0548x over previous
#include <cuda_runtime.h>

#define BATCH 128
#define CDIM 512
#define SDIM 128
#define MDIM 512

// ---------------- scratch (static device globals; no allocation) ----------------
__device__ float g_xg[BATCH * CDIM * SDIM];    // 33.5 MB  (Gt-projected query, bias w folded)
__device__ float g_vwf[BATCH * CDIM * SDIM];   // 33.5 MB  (value @ Weff^T + beff)
__device__ float g_gt[SDIM * SDIM];            // Gt[s'][s] = SC * sum_m Wq[m,s] Wk[m,s']
__device__ float g_w[SDIM];                    // SC * Wk^T bq
__device__ float g_weff[SDIM * SDIM];          // Weff[s_out][s_in] = sum_m Wf[s_out,m] Wv[m,s_in]
__device__ float g_beff[SDIM];                 // Wf bv + bf
__device__ float g_psum[CDIM * BATCH];
__device__ float g_psumsq[CDIM * BATCH];
__device__ float g_scale[CDIM];
__device__ float g_shift[CDIM];

// ---------------- K0: prep small matrices ----------------
__global__ void prep_kernel(const float* __restrict__ Wq, const float* __restrict__ bq,
                            const float* __restrict__ Wk, const float* __restrict__ bk,
                            const float* __restrict__ Wv, const float* __restrict__ bv,
                            const float* __restrict__ Wf, const float* __restrict__ bf) {
    const float SC = 0.04419417382415922f;   // 512^-0.5
    int n = blockIdx.x;    // s' for Gt, s_out for Weff
    int k = threadIdx.x;   // s  for Gt, s_in  for Weff
    float g = 0.f, e = 0.f;
    for (int m = 0; m < MDIM; m++) {
        g += Wq[m * SDIM + k] * Wk[m * SDIM + n];
        e += Wf[n * MDIM + m] * Wv[m * SDIM + k];
    }
    g_gt[n * SDIM + k] = g * SC;
    g_weff[n * SDIM + k] = e;
    if (k == 0) {
        float w = 0.f, b = bf[n];
        for (int m = 0; m < MDIM; m++) {
            w += Wk[m * SDIM + n] * bq[m];
            b += Wf[n * MDIM + m] * bv[m];
        }
        g_w[n] = w * SC;
        g_beff[n] = b;
    }
}

// ---------------- K1: NT projection GEMM (128-wide output) ----------------
// out[row, n] = sum_k X[row,k] * W[n,k] + bias[n];  K = S = 128, ncols = 128
// sel: 0 -> g_xg (W=g_gt, bias=g_w), 1 -> g_vwf (W=g_weff, bias=g_beff)
__global__ __launch_bounds__(256, 2) void proj_kernel(const float* __restrict__ X, int sel) {
    __shared__ float Xs[32][132];   // [k][row]
    __shared__ float Ws[32][132];   // [k][n]
    float* out = (sel == 0) ? g_xg : g_vwf;
    const float* W = (sel == 0) ? g_gt : g_weff;
    const float* bias = (sel == 0) ? g_w : g_beff;

    int tx = threadIdx.x, ty = threadIdx.y;
    int tid = ty * 16 + tx;
    int row0 = blockIdx.y * 128;

    float acc[8][8];
    #pragma unroll
    for (int i = 0; i < 8; i++)
        #pragma unroll
        for (int j = 0; j < 8; j++) acc[i][j] = 0.f;

    for (int kc = 0; kc < 4; kc++) {
        __syncthreads();
        #pragma unroll
        for (int t = 0; t < 4; t++) {
            int f = tid + t * 256;       // 0..1023
            int r = f >> 3;              // 0..127
            int k0 = (f & 7) * 4;        // 0..28
            float4 v = *(const float4*)(X + (size_t)(row0 + r) * SDIM + kc * 32 + k0);
            Xs[k0 + 0][r] = v.x; Xs[k0 + 1][r] = v.y; Xs[k0 + 2][r] = v.z; Xs[k0 + 3][r] = v.w;
            float4 w = *(const float4*)(W + (size_t)r * SDIM + kc * 32 + k0);
            Ws[k0 + 0][r] = w.x; Ws[k0 + 1][r] = w.y; Ws[k0 + 2][r] = w.z; Ws[k0 + 3][r] = w.w;
        }
        __syncthreads();
        #pragma unroll
        for (int k = 0; k < 32; k++) {
            float a[8], bb[8];
            *(float4*)(a)     = *(const float4*)&Xs[k][ty * 8];
            *(float4*)(a + 4) = *(const float4*)&Xs[k][ty * 8 + 4];
            *(float4*)(bb)     = *(const float4*)&Ws[k][tx * 8];
            *(float4*)(bb + 4) = *(const float4*)&Ws[k][tx * 8 + 4];
            #pragma unroll
            for (int i = 0; i < 8; i++)
                #pragma unroll
                for (int j = 0; j < 8; j++) acc[i][j] += a[i] * bb[j];
        }
    }

    float bvv[8];
    #pragma unroll
    for (int j = 0; j < 8; j++) bvv[j] = bias[tx * 8 + j];
    #pragma unroll
    for (int i = 0; i < 8; i++) {
        int row = row0 + ty * 8 + i;
        float4 o0, o1;
        o0.x = acc[i][0] + bvv[0]; o0.y = acc[i][1] + bvv[1];
        o0.z = acc[i][2] + bvv[2]; o0.w = acc[i][3] + bvv[3];
        o1.x = acc[i][4] + bvv[4]; o1.y = acc[i][5] + bvv[5];
        o1.z = acc[i][6] + bvv[6]; o1.w = acc[i][7] + bvv[7];
        *(float4*)(out + (size_t)row * SDIM + tx * 8)     = o0;
        *(float4*)(out + (size_t)row * SDIM + tx * 8 + 4) = o1;
    }
}

// ---------------- K2: scores NT GEMM (per batch), raw logits -> att ----------------
// att[b,i,j] = sum_k Xg[b,i,k] * key[b,j,k];  K = 128
__global__ __launch_bounds__(256, 2) void scores_kernel(const float* __restrict__ key,
                                                        float* __restrict__ att) {
    __shared__ float Xs[32][132];
    __shared__ float Ks[32][132];

    int b = blockIdx.z;
    int row0 = blockIdx.y * 128;
    int n0 = blockIdx.x * 128;
    int tx = threadIdx.x, ty = threadIdx.y;
    int tid = ty * 16 + tx;

    const float* xb = g_xg + (size_t)b * CDIM * SDIM + (size_t)row0 * SDIM;
    const float* kb = key + (size_t)b * CDIM * SDIM + (size_t)n0 * SDIM;

    float acc[8][8];
    #pragma unroll
    for (int i = 0; i < 8; i++)
        #pragma unroll
        for (int j = 0; j < 8; j++) acc[i][j] = 0.f;

    for (int kc = 0; kc < 4; kc++) {
        __syncthreads();
        #pragma unroll
        for (int t = 0; t < 4; t++) {
            int f = tid + t * 256;
            int r = f >> 3;
            int k0 = (f & 7) * 4;
            float4 v = *(const float4*)(xb + (size_t)r * SDIM + kc * 32 + k0);
            Xs[k0 + 0][r] = v.x; Xs[k0 + 1][r] = v.y; Xs[k0 + 2][r] = v.z; Xs[k0 + 3][r] = v.w;
            float4 w = *(const float4*)(kb + (size_t)r * SDIM + kc * 32 + k0);
            Ks[k0 + 0][r] = w.x; Ks[k0 + 1][r] = w.y; Ks[k0 + 2][r] = w.z; Ks[k0 + 3][r] = w.w;
        }
        __syncthreads();
        #pragma unroll
        for (int k = 0; k < 32; k++) {
            float a[8], bb[8];
            *(float4*)(a)     = *(const float4*)&Xs[k][ty * 8];
            *(float4*)(a + 4) = *(const float4*)&Xs[k][ty * 8 + 4];
            *(float4*)(bb)     = *(const float4*)&Ks[k][tx * 8];
            *(float4*)(bb + 4) = *(const float4*)&Ks[k][tx * 8 + 4];
            #pragma unroll
            for (int i = 0; i < 8; i++)
                #pragma unroll
                for (int j = 0; j < 8; j++) acc[i][j] += a[i] * bb[j];
        }
    }

    float* ap = att + (size_t)b * CDIM * CDIM + (size_t)row0 * CDIM + n0;
    #pragma unroll
    for (int i = 0; i < 8; i++) {
        int r = ty * 8 + i;
        float4 o0, o1;
        o0.x = acc[i][0]; o0.y = acc[i][1]; o0.z = acc[i][2]; o0.w = acc[i][3];
        o1.x = acc[i][4]; o1.y = acc[i][5]; o1.z = acc[i][6]; o1.w = acc[i][7];
        *(float4*)(ap + (size_t)r * CDIM + tx * 8)     = o0;
        *(float4*)(ap + (size_t)r * CDIM + tx * 8 + 4) = o1;
    }
}

// ---------------- K3: warp-per-row softmax, in place ----------------
__global__ __launch_bounds__(256) void softmax_kernel(float* __restrict__ att) {
    size_t row = ((size_t)blockIdx.x * 256 + threadIdx.x) >> 5;
    int lane = threadIdx.x & 31;
    float4* rp = (float4*)(att + row * CDIM);

    float4 v[4];
    #pragma unroll
    for (int i = 0; i < 4; i++) v[i] = rp[lane + i * 32];

    float m = -3.4e38f;
    #pragma unroll
    for (int i = 0; i < 4; i++) {
        m = fmaxf(m, fmaxf(fmaxf(v[i].x, v[i].y), fmaxf(v[i].z, v[i].w)));
    }
    #pragma unroll
    for (int off = 16; off; off >>= 1) m = fmaxf(m, __shfl_xor_sync(0xffffffffu, m, off));

    float s = 0.f;
    #pragma unroll
    for (int i = 0; i < 4; i++) {
        v[i].x = __expf(v[i].x - m); s += v[i].x;
        v[i].y = __expf(v[i].y - m); s += v[i].y;
        v[i].z = __expf(v[i].z - m); s += v[i].z;
        v[i].w = __expf(v[i].w - m); s += v[i].w;
    }
    #pragma unroll
    for (int off = 16; off; off >>= 1) s += __shfl_xor_sync(0xffffffffu, s, off);

    float inv = 1.0f / s;
    #pragma unroll
    for (int i = 0; i < 4; i++) {
        v[i].x *= inv; v[i].y *= inv; v[i].z *= inv; v[i].w *= inv;
        rp[lane + i * 32] = v[i];
    }
}

// ---------------- K4: context NN GEMM + BN partial sums ----------------
// outp[b,c,s] = sum_j A[b,c,j] * vwf[b,j,s];  K=512, N=128
__global__ __launch_bounds__(256, 2) void ctx_kernel(const float* __restrict__ att,
                                                     float* __restrict__ outp) {
    __shared__ float As[32][132];   // [j_local][row]
    __shared__ float Bs[32][132];   // [j_local][s]

    int b = blockIdx.y;
    int row0 = blockIdx.x * 128;
    int tx = threadIdx.x, ty = threadIdx.y;
    int tid = ty * 16 + tx;

    const float* ab = att + (size_t)b * CDIM * CDIM + (size_t)row0 * CDIM;
    const float* vb = g_vwf + (size_t)b * CDIM * SDIM;

    float acc[8][8];
    #pragma unroll
    for (int i = 0; i < 8; i++)
        #pragma unroll
        for (int j = 0; j < 8; j++) acc[i][j] = 0.f;

    for (int kc = 0; kc < 16; kc++) {
        __syncthreads();
        #pragma unroll
        for (int t = 0; t < 4; t++) {
            int f = tid + t * 256;       // 0..1023
            int r = f >> 3;              // 0..127
            int k0 = (f & 7) * 4;
            float4 v = *(const float4*)(ab + (size_t)r * CDIM + kc * 32 + k0);
            As[k0 + 0][r] = v.x; As[k0 + 1][r] = v.y; As[k0 + 2][r] = v.z; As[k0 + 3][r] = v.w;
            int jj = f >> 5;             // 0..31
            int s0 = (f & 31) * 4;       // 0..124
            float4 u = *(const float4*)(vb + (size_t)(kc * 32 + jj) * SDIM + s0);
            *(float4*)&Bs[jj][s0] = u;
        }
        __syncthreads();
        #pragma unroll
        for (int k = 0; k < 32; k++) {
            float a[8], bb[8];
            *(float4*)(a)     = *(const float4*)&As[k][ty * 8];
            *(float4*)(a + 4) = *(const float4*)&As[k][ty * 8 + 4];
            *(float4*)(bb)     = *(const float4*)&Bs[k][tx * 8];
            *(float4*)(bb + 4) = *(const float4*)&Bs[k][tx * 8 + 4];
            #pragma unroll
            for (int i = 0; i < 8; i++)
                #pragma unroll
                for (int j = 0; j < 8; j++) acc[i][j] += a[i] * bb[j];
        }
    }

    // write pre-BN output
    #pragma unroll
    for (int i = 0; i < 8; i++) {
        int r = row0 + ty * 8 + i;
        float* p = outp + (size_t)b * CDIM * SDIM + (size_t)r * SDIM + tx * 8;
        float4 o0, o1;
        o0.x = acc[i][0]; o0.y = acc[i][1]; o0.z = acc[i][2]; o0.w = acc[i][3];
        o1.x = acc[i][4]; o1.y = acc[i][5]; o1.z = acc[i][6]; o1.w = acc[i][7];
        *(float4*)(p)     = o0;
        *(float4*)(p + 4) = o1;
    }

    // deterministic BN partials: this block owns (batch b, channels row0..row0+127, all s)
    #pragma unroll
    for (int i = 0; i < 8; i++) {
        float s1 = 0.f, s2 = 0.f;
        #pragma unroll
        for (int j = 0; j < 8; j++) { float v = acc[i][j]; s1 += v; s2 += v * v; }
        #pragma unroll
        for (int off = 8; off; off >>= 1) {
            s1 += __shfl_xor_sync(0xffffffffu, s1, off);
            s2 += __shfl_xor_sync(0xffffffffu, s2, off);
        }
        if (tx == 0) {
            int c = row0 + ty * 8 + i;
            g_psum[(size_t)c * BATCH + b] = s1;
            g_psumsq[(size_t)c * BATCH + b] = s2;
        }
    }
}

// ---------------- K5: finalize BN stats ----------------
__global__ void stats_kernel(const float* __restrict__ gamma, const float* __restrict__ beta) {
    int c = threadIdx.x;
    float s = 0.f, ss = 0.f;
    for (int b = 0; b < BATCH; b++) {
        s += g_psum[(size_t)c * BATCH + b];
        ss += g_psumsq[(size_t)c * BATCH + b];
    }
    const float inv_n = 1.0f / (float)(BATCH * SDIM);
    float mean = s * inv_n;
    float var = ss * inv_n - mean * mean;
    float sc = gamma[c] * rsqrtf(var + 1e-5f);
    g_scale[c] = sc;
    g_shift[c] = beta[c] - mean * sc;
}

// ---------------- K6: apply BN + relu + residual ----------------
__global__ void apply_kernel(const float* __restrict__ value, float* __restrict__ out) {
    int idx = blockIdx.x * 256 + threadIdx.x;        // float4 index
    int c = (idx >> 5) & (CDIM - 1);                 // 32 float4 per (b,c) row
    float sc = g_scale[c], sh = g_shift[c];
    float4 o = ((const float4*)out)[idx];
    float4 v = ((const float4*)value)[idx];
    o.x = fmaxf(o.x * sc + sh, 0.f) + v.x;
    o.y = fmaxf(o.y * sc + sh, 0.f) + v.y;
    o.z = fmaxf(o.z * sc + sh, 0.f) + v.z;
    o.w = fmaxf(o.w * sc + sh, 0.f) + v.w;
    ((float4*)out)[idx] = o;
}

// ---------------- launch ----------------
extern "C" void kernel_launch(void* const* d_in, const int* in_sizes, int n_in,
                              void* d_out, int out_size) {
    const float* query = (const float*)d_in[0];
    const float* key   = (const float*)d_in[1];
    const float* value = (const float*)d_in[2];
    const float* Wq = (const float*)d_in[3];
    const float* bq = (const float*)d_in[4];
    const float* Wk = (const float*)d_in[5];
    const float* bk = (const float*)d_in[6];
    const float* Wv = (const float*)d_in[7];
    const float* bv = (const float*)d_in[8];
    const float* Wf = (const float*)d_in[9];
    const float* bf = (const float*)d_in[10];
    const float* gamma = (const float*)d_in[11];
    const float* beta  = (const float*)d_in[12];

    float* out = (float*)d_out;                               // [B,C,S]
    float* att = out + (size_t)BATCH * CDIM * SDIM;           // [B,C,C]

    dim3 blk(16, 16);
    prep_kernel<<<SDIM, SDIM>>>(Wq, bq, Wk, bk, Wv, bv, Wf, bf);
    proj_kernel<<<dim3(1, 512), blk>>>(query, 0);
    proj_kernel<<<dim3(1, 512), blk>>>(value, 1);
    scores_kernel<<<dim3(4, 4, BATCH), blk>>>(key, att);
    softmax_kernel<<<8192, 256>>>(att);
    ctx_kernel<<<dim3(4, BATCH), blk>>>(att, out);
    stats_kernel<<<1, CDIM>>>(gamma, beta);
    apply_kernel<<<8192, 256>>>(value, out);
}

// round 8
// speedup vs baseline: 2.7970x; 1.3409x over previous
#include <cuda_runtime.h>
#include <cuda_bf16.h>
#include <cstdint>

#define BATCH 128
#define CDIM 512
#define SDIM 128
#define MDIM 512
#define PAD 20   // b32 row stride for smem fragment tiles (bank-conflict-free)

// ---------------- scratch (static device globals; no allocation) ----------------
__device__ __nv_bfloat16 g_xgh[BATCH * CDIM * SDIM];
__device__ __nv_bfloat16 g_xgl[BATCH * CDIM * SDIM];
__device__ __nv_bfloat16 g_keyh[BATCH * CDIM * SDIM];
__device__ __nv_bfloat16 g_keyl[BATCH * CDIM * SDIM];
__device__ __nv_bfloat16 g_vwfTh[BATCH * SDIM * CDIM]; // [b][s][c]
__device__ __nv_bfloat16 g_vwfTl[BATCH * SDIM * CDIM];
__device__ __nv_bfloat16 g_atth[(size_t)BATCH * CDIM * CDIM];
__device__ __nv_bfloat16 g_attl[(size_t)BATCH * CDIM * CDIM];
__device__ float g_gt[SDIM * SDIM];
__device__ float g_w[SDIM];
__device__ float g_weff[SDIM * SDIM];
__device__ float g_beff[SDIM];
__device__ float g_psum[CDIM * BATCH];
__device__ float g_psumsq[CDIM * BATCH];
__device__ float g_scale[CDIM];
__device__ float g_shift[CDIM];

// ---------------- helpers ----------------
__device__ __forceinline__ void split_bf16(float v, uint16_t& h, uint16_t& l) {
    __nv_bfloat16 hb = __float2bfloat16(v);
    h = *(uint16_t*)&hb;
    __nv_bfloat16 lb = __float2bfloat16(v - __bfloat162float(hb));
    l = *(uint16_t*)&lb;
}

// m16n8k16 bf16 MMA, fp32 accumulate (sm_80+; HMMA on sm_103a)
__device__ __forceinline__ void mma16816(float* c, const uint32_t* a, uint32_t b0, uint32_t b1) {
    asm volatile(
        "mma.sync.aligned.m16n8k16.row.col.f32.bf16.bf16.f32 "
        "{%0,%1,%2,%3}, {%4,%5,%6,%7}, {%8,%9}, {%0,%1,%2,%3};\n"
        : "+f"(c[0]), "+f"(c[1]), "+f"(c[2]), "+f"(c[3])
        : "r"(a[0]), "r"(a[1]), "r"(a[2]), "r"(a[3]), "r"(b0), "r"(b1));
}

// ---------------- K0: prep small matrices ----------------
__global__ void prep_kernel(const float* __restrict__ Wq, const float* __restrict__ bq,
                            const float* __restrict__ Wk, const float* __restrict__ bk,
                            const float* __restrict__ Wv, const float* __restrict__ bv,
                            const float* __restrict__ Wf, const float* __restrict__ bf) {
    const float SC = 0.04419417382415922f;   // 512^-0.5
    int n = blockIdx.x;
    int k = threadIdx.x;
    float g = 0.f, e = 0.f;
    for (int m = 0; m < MDIM; m++) {
        g += Wq[m * SDIM + k] * Wk[m * SDIM + n];
        e += Wf[n * MDIM + m] * Wv[m * SDIM + k];
    }
    g_gt[n * SDIM + k] = g * SC;
    g_weff[n * SDIM + k] = e;
    if (k == 0) {
        float w = 0.f, b = bf[n];
        for (int m = 0; m < MDIM; m++) {
            w += Wk[m * SDIM + n] * bq[m];
            b += Wf[n * MDIM + m] * bv[m];
        }
        g_w[n] = w * SC;
        g_beff[n] = b;
    }
}

// ---------------- K1: SIMT projection -> split-bf16 outputs ----------------
// sel 0: Xg = query*Gt^T + w  -> g_xgh/g_xgl  [b*c][s'] row-major
// sel 1: vwf = value*Weff^T + beff -> g_vwfTh/l TRANSPOSED [b][s][c]
__global__ __launch_bounds__(256, 2) void proj_kernel(const float* __restrict__ X, int sel) {
    __shared__ float Xs[32][132];
    __shared__ float Ws[32][132];
    const float* W = (sel == 0) ? g_gt : g_weff;
    const float* bias = (sel == 0) ? g_w : g_beff;

    int tx = threadIdx.x, ty = threadIdx.y;
    int tid = ty * 16 + tx;
    int row0 = blockIdx.y * 128;

    float acc[8][8];
    #pragma unroll
    for (int i = 0; i < 8; i++)
        #pragma unroll
        for (int j = 0; j < 8; j++) acc[i][j] = 0.f;

    for (int kc = 0; kc < 4; kc++) {
        __syncthreads();
        #pragma unroll
        for (int t = 0; t < 4; t++) {
            int f = tid + t * 256;
            int r = f >> 3;
            int k0 = (f & 7) * 4;
            float4 v = *(const float4*)(X + (size_t)(row0 + r) * SDIM + kc * 32 + k0);
            Xs[k0 + 0][r] = v.x; Xs[k0 + 1][r] = v.y; Xs[k0 + 2][r] = v.z; Xs[k0 + 3][r] = v.w;
            float4 w = *(const float4*)(W + (size_t)r * SDIM + kc * 32 + k0);
            Ws[k0 + 0][r] = w.x; Ws[k0 + 1][r] = w.y; Ws[k0 + 2][r] = w.z; Ws[k0 + 3][r] = w.w;
        }
        __syncthreads();
        #pragma unroll
        for (int k = 0; k < 32; k++) {
            float a[8], bb[8];
            *(float4*)(a)      = *(const float4*)&Xs[k][ty * 8];
            *(float4*)(a + 4)  = *(const float4*)&Xs[k][ty * 8 + 4];
            *(float4*)(bb)     = *(const float4*)&Ws[k][tx * 8];
            *(float4*)(bb + 4) = *(const float4*)&Ws[k][tx * 8 + 4];
            #pragma unroll
            for (int i = 0; i < 8; i++)
                #pragma unroll
                for (int j = 0; j < 8; j++) acc[i][j] += a[i] * bb[j];
        }
    }

    float bvv[8];
    #pragma unroll
    for (int j = 0; j < 8; j++) bvv[j] = bias[tx * 8 + j];
    #pragma unroll
    for (int i = 0; i < 8; i++)
        #pragma unroll
        for (int j = 0; j < 8; j++) acc[i][j] += bvv[j];

    if (sel == 0) {
        #pragma unroll
        for (int i = 0; i < 8; i++) {
            int row = row0 + ty * 8 + i;
            uint32_t hw[4], lw[4];
            #pragma unroll
            for (int q = 0; q < 4; q++) {
                uint16_t h0, l0, h1, l1;
                split_bf16(acc[i][2 * q], h0, l0);
                split_bf16(acc[i][2 * q + 1], h1, l1);
                hw[q] = (uint32_t)h0 | ((uint32_t)h1 << 16);
                lw[q] = (uint32_t)l0 | ((uint32_t)l1 << 16);
            }
            *(uint4*)(g_xgh + (size_t)row * SDIM + tx * 8) = make_uint4(hw[0], hw[1], hw[2], hw[3]);
            *(uint4*)(g_xgl + (size_t)row * SDIM + tx * 8) = make_uint4(lw[0], lw[1], lw[2], lw[3]);
        }
    } else {
        int b = row0 >> 9;
        int c0 = (row0 & 511) + ty * 8;
        #pragma unroll
        for (int j = 0; j < 8; j++) {
            int s = tx * 8 + j;
            uint32_t hw[4], lw[4];
            #pragma unroll
            for (int q = 0; q < 4; q++) {
                uint16_t h0, l0, h1, l1;
                split_bf16(acc[2 * q][j], h0, l0);
                split_bf16(acc[2 * q + 1][j], h1, l1);
                hw[q] = (uint32_t)h0 | ((uint32_t)h1 << 16);
                lw[q] = (uint32_t)l0 | ((uint32_t)l1 << 16);
            }
            size_t base = ((size_t)b * SDIM + s) * CDIM + c0;
            *(uint4*)(g_vwfTh + base) = make_uint4(hw[0], hw[1], hw[2], hw[3]);
            *(uint4*)(g_vwfTl + base) = make_uint4(lw[0], lw[1], lw[2], lw[3]);
        }
    }
}

// ---------------- K2: split key into bf16 hi/lo ----------------
__global__ void keysplit_kernel(const float* __restrict__ key) {
    int idx = blockIdx.x * 256 + threadIdx.x;        // float4 index
    float4 v = ((const float4*)key)[idx];
    uint16_t h0, l0, h1, l1, h2, l2, h3, l3;
    split_bf16(v.x, h0, l0); split_bf16(v.y, h1, l1);
    split_bf16(v.z, h2, l2); split_bf16(v.w, h3, l3);
    uint2 hu, lu;
    hu.x = (uint32_t)h0 | ((uint32_t)h1 << 16); hu.y = (uint32_t)h2 | ((uint32_t)h3 << 16);
    lu.x = (uint32_t)l0 | ((uint32_t)l1 << 16); lu.y = (uint32_t)l2 | ((uint32_t)l3 << 16);
    ((uint2*)g_keyh)[idx] = hu;
    ((uint2*)g_keyl)[idx] = lu;
}

// ---------------- K3: scores GEMM via mma.sync (split-bf16, 3 products) ----------------
// logits[b, i0+128), n0+128) = Xg_tile @ key_tile^T;  K = 128
__global__ __launch_bounds__(256, 2) void scores_mma(float* __restrict__ att) {
    __shared__ uint32_t Ah[128 * PAD], Al[128 * PAD], Bh[128 * PAD], Bl[128 * PAD];
    int tid = threadIdx.x, lane = tid & 31, wid = tid >> 5;
    int wm = wid & 3, wn = wid >> 2;              // warp tile: 32 rows x 64 cols
    int b = blockIdx.z, i0 = blockIdx.y * 128, n0 = blockIdx.x * 128;

    const __nv_bfloat16* pAh = g_xgh + ((size_t)b * CDIM + i0) * SDIM;
    const __nv_bfloat16* pAl = g_xgl + ((size_t)b * CDIM + i0) * SDIM;
    const __nv_bfloat16* pBh = g_keyh + ((size_t)b * CDIM + n0) * SDIM;
    const __nv_bfloat16* pBl = g_keyl + ((size_t)b * CDIM + n0) * SDIM;

    float acc[2][8][4];
    #pragma unroll
    for (int mt = 0; mt < 2; mt++)
        #pragma unroll
        for (int nt = 0; nt < 8; nt++)
            #pragma unroll
            for (int q = 0; q < 4; q++) acc[mt][nt][q] = 0.f;

    for (int kc = 0; kc < 4; kc++) {
        __syncthreads();
        #pragma unroll
        for (int t2 = 0; t2 < 2; t2++) {
            int f = tid + t2 * 256;               // 0..511
            int row = f >> 2, q = f & 3;          // 4 uint4 per 32-bf16 row chunk
            size_t so = (size_t)row * SDIM + kc * 32 + q * 8;
            *(uint4*)&Ah[row * PAD + q * 4] = *(const uint4*)(pAh + so);
            *(uint4*)&Al[row * PAD + q * 4] = *(const uint4*)(pAl + so);
            *(uint4*)&Bh[row * PAD + q * 4] = *(const uint4*)(pBh + so);
            *(uint4*)&Bl[row * PAD + q * 4] = *(const uint4*)(pBl + so);
        }
        __syncthreads();
        #pragma unroll
        for (int ks = 0; ks < 2; ks++) {
            int cb = ks * 8 + (lane & 3);
            uint32_t ah[2][4], al[2][4];
            #pragma unroll
            for (int mt = 0; mt < 2; mt++) {
                int r = (wm * 32 + mt * 16 + (lane >> 2)) * PAD;
                ah[mt][0] = Ah[r + cb];           ah[mt][1] = Ah[r + 8 * PAD + cb];
                ah[mt][2] = Ah[r + cb + 4];       ah[mt][3] = Ah[r + 8 * PAD + cb + 4];
                al[mt][0] = Al[r + cb];           al[mt][1] = Al[r + 8 * PAD + cb];
                al[mt][2] = Al[r + cb + 4];       al[mt][3] = Al[r + 8 * PAD + cb + 4];
            }
            #pragma unroll
            for (int nt = 0; nt < 8; nt++) {
                int n = (wn * 64 + nt * 8 + (lane >> 2)) * PAD;
                uint32_t bh0 = Bh[n + cb], bh1 = Bh[n + cb + 4];
                uint32_t bl0 = Bl[n + cb], bl1 = Bl[n + cb + 4];
                #pragma unroll
                for (int mt = 0; mt < 2; mt++) {
                    mma16816(acc[mt][nt], ah[mt], bh0, bh1);
                    mma16816(acc[mt][nt], ah[mt], bl0, bl1);
                    mma16816(acc[mt][nt], al[mt], bh0, bh1);
                }
            }
        }
    }

    // write raw logits
    #pragma unroll
    for (int mt = 0; mt < 2; mt++) {
        int grow = i0 + wm * 32 + mt * 16 + (lane >> 2);
        #pragma unroll
        for (int nt = 0; nt < 8; nt++) {
            int gcol = n0 + wn * 64 + nt * 8 + (lane & 3) * 2;
            float* p = att + ((size_t)b * CDIM + grow) * CDIM + gcol;
            *(float2*)p = make_float2(acc[mt][nt][0], acc[mt][nt][1]);
            *(float2*)(p + 8 * CDIM) = make_float2(acc[mt][nt][2], acc[mt][nt][3]);
        }
    }
}

// ---------------- K4: softmax, writes fp32 att + bf16 hi/lo ----------------
__global__ __launch_bounds__(256) void softmax_kernel(float* __restrict__ att) {
    size_t row = ((size_t)blockIdx.x * 256 + threadIdx.x) >> 5;
    int lane = threadIdx.x & 31;
    float4* rp = (float4*)(att + row * CDIM);

    float4 v[4];
    #pragma unroll
    for (int i = 0; i < 4; i++) v[i] = rp[lane + i * 32];

    float m = -3.4e38f;
    #pragma unroll
    for (int i = 0; i < 4; i++)
        m = fmaxf(m, fmaxf(fmaxf(v[i].x, v[i].y), fmaxf(v[i].z, v[i].w)));
    #pragma unroll
    for (int off = 16; off; off >>= 1) m = fmaxf(m, __shfl_xor_sync(0xffffffffu, m, off));

    float s = 0.f;
    #pragma unroll
    for (int i = 0; i < 4; i++) {
        v[i].x = __expf(v[i].x - m); s += v[i].x;
        v[i].y = __expf(v[i].y - m); s += v[i].y;
        v[i].z = __expf(v[i].z - m); s += v[i].z;
        v[i].w = __expf(v[i].w - m); s += v[i].w;
    }
    #pragma unroll
    for (int off = 16; off; off >>= 1) s += __shfl_xor_sync(0xffffffffu, s, off);

    float inv = 1.0f / s;
    uint2* hrow = (uint2*)(g_atth + row * CDIM);
    uint2* lrow = (uint2*)(g_attl + row * CDIM);
    #pragma unroll
    for (int i = 0; i < 4; i++) {
        v[i].x *= inv; v[i].y *= inv; v[i].z *= inv; v[i].w *= inv;
        rp[lane + i * 32] = v[i];
        uint16_t h0, l0, h1, l1, h2, l2, h3, l3;
        split_bf16(v[i].x, h0, l0); split_bf16(v[i].y, h1, l1);
        split_bf16(v[i].z, h2, l2); split_bf16(v[i].w, h3, l3);
        uint2 hu, lu;
        hu.x = (uint32_t)h0 | ((uint32_t)h1 << 16); hu.y = (uint32_t)h2 | ((uint32_t)h3 << 16);
        lu.x = (uint32_t)l0 | ((uint32_t)l1 << 16); lu.y = (uint32_t)l2 | ((uint32_t)l3 << 16);
        hrow[lane + i * 32] = hu;
        lrow[lane + i * 32] = lu;
    }
}

// ---------------- K5: context GEMM via mma.sync + fused BN partials ----------------
// out[b, c0+128), s] = sum_j att[b,c,j] * vwfT[b,s,j];  K = 512
__global__ __launch_bounds__(256, 2) void ctx_mma(float* __restrict__ outp) {
    __shared__ uint32_t Ah[128 * PAD], Al[128 * PAD], Bh[128 * PAD], Bl[128 * PAD];
    __shared__ float redS[128][2], redQ[128][2];
    int tid = threadIdx.x, lane = tid & 31, wid = tid >> 5;
    int wm = wid & 3, wn = wid >> 2;
    int b = blockIdx.y, c0 = blockIdx.x * 128;

    const __nv_bfloat16* pAh = g_atth + ((size_t)b * CDIM + c0) * CDIM;
    const __nv_bfloat16* pAl = g_attl + ((size_t)b * CDIM + c0) * CDIM;
    const __nv_bfloat16* pBh = g_vwfTh + (size_t)b * SDIM * CDIM;
    const __nv_bfloat16* pBl = g_vwfTl + (size_t)b * SDIM * CDIM;

    float acc[2][8][4];
    #pragma unroll
    for (int mt = 0; mt < 2; mt++)
        #pragma unroll
        for (int nt = 0; nt < 8; nt++)
            #pragma unroll
            for (int q = 0; q < 4; q++) acc[mt][nt][q] = 0.f;

    for (int kc = 0; kc < 16; kc++) {
        __syncthreads();
        #pragma unroll
        for (int t2 = 0; t2 < 2; t2++) {
            int f = tid + t2 * 256;
            int row = f >> 2, q = f & 3;
            size_t so = (size_t)row * CDIM + kc * 32 + q * 8;
            *(uint4*)&Ah[row * PAD + q * 4] = *(const uint4*)(pAh + so);
            *(uint4*)&Al[row * PAD + q * 4] = *(const uint4*)(pAl + so);
            *(uint4*)&Bh[row * PAD + q * 4] = *(const uint4*)(pBh + so);
            *(uint4*)&Bl[row * PAD + q * 4] = *(const uint4*)(pBl + so);
        }
        __syncthreads();
        #pragma unroll
        for (int ks = 0; ks < 2; ks++) {
            int cb = ks * 8 + (lane & 3);
            uint32_t ah[2][4], al[2][4];
            #pragma unroll
            for (int mt = 0; mt < 2; mt++) {
                int r = (wm * 32 + mt * 16 + (lane >> 2)) * PAD;
                ah[mt][0] = Ah[r + cb];           ah[mt][1] = Ah[r + 8 * PAD + cb];
                ah[mt][2] = Ah[r + cb + 4];       ah[mt][3] = Ah[r + 8 * PAD + cb + 4];
                al[mt][0] = Al[r + cb];           al[mt][1] = Al[r + 8 * PAD + cb];
                al[mt][2] = Al[r + cb + 4];       al[mt][3] = Al[r + 8 * PAD + cb + 4];
            }
            #pragma unroll
            for (int nt = 0; nt < 8; nt++) {
                int n = (wn * 64 + nt * 8 + (lane >> 2)) * PAD;
                uint32_t bh0 = Bh[n + cb], bh1 = Bh[n + cb + 4];
                uint32_t bl0 = Bl[n + cb], bl1 = Bl[n + cb + 4];
                #pragma unroll
                for (int mt = 0; mt < 2; mt++) {
                    mma16816(acc[mt][nt], ah[mt], bh0, bh1);
                    mma16816(acc[mt][nt], ah[mt], bl0, bl1);
                    mma16816(acc[mt][nt], al[mt], bh0, bh1);
                }
            }
        }
    }

    // write output + per-row BN partial sums
    #pragma unroll
    for (int mt = 0; mt < 2; mt++) {
        int grow = c0 + wm * 32 + mt * 16 + (lane >> 2);
        float sA = 0.f, qA = 0.f, sB = 0.f, qB = 0.f;
        #pragma unroll
        for (int nt = 0; nt < 8; nt++) {
            int gcol = wn * 64 + nt * 8 + (lane & 3) * 2;
            float* p = outp + ((size_t)b * CDIM + grow) * SDIM + gcol;
            float v0 = acc[mt][nt][0], v1 = acc[mt][nt][1];
            float v2 = acc[mt][nt][2], v3 = acc[mt][nt][3];
            *(float2*)p = make_float2(v0, v1);
            *(float2*)(p + 8 * SDIM) = make_float2(v2, v3);
            sA += v0 + v1; qA += v0 * v0 + v1 * v1;
            sB += v2 + v3; qB += v2 * v2 + v3 * v3;
        }
        // reduce over the 4 lanes sharing the same row (lane&3)
        #pragma unroll
        for (int off = 1; off <= 2; off <<= 1) {
            sA += __shfl_xor_sync(0xffffffffu, sA, off);
            qA += __shfl_xor_sync(0xffffffffu, qA, off);
            sB += __shfl_xor_sync(0xffffffffu, sB, off);
            qB += __shfl_xor_sync(0xffffffffu, qB, off);
        }
        if ((lane & 3) == 0) {
            int lr = wm * 32 + mt * 16 + (lane >> 2);
            redS[lr][wn] = sA;     redQ[lr][wn] = qA;
            redS[lr + 8][wn] = sB; redQ[lr + 8][wn] = qB;
        }
    }
    __syncthreads();
    if (tid < 128) {
        int c = c0 + tid;
        g_psum[(size_t)c * BATCH + b] = redS[tid][0] + redS[tid][1];
        g_psumsq[(size_t)c * BATCH + b] = redQ[tid][0] + redQ[tid][1];
    }
}

// ---------------- K6: finalize BN stats ----------------
__global__ void stats_kernel(const float* __restrict__ gamma, const float* __restrict__ beta) {
    int c = threadIdx.x;
    float s = 0.f, ss = 0.f;
    for (int b = 0; b < BATCH; b++) {
        s += g_psum[(size_t)c * BATCH + b];
        ss += g_psumsq[(size_t)c * BATCH + b];
    }
    const float inv_n = 1.0f / (float)(BATCH * SDIM);
    float mean = s * inv_n;
    float var = ss * inv_n - mean * mean;
    float sc = gamma[c] * rsqrtf(var + 1e-5f);
    g_scale[c] = sc;
    g_shift[c] = beta[c] - mean * sc;
}

// ---------------- K7: apply BN + relu + residual ----------------
__global__ void apply_kernel(const float* __restrict__ value, float* __restrict__ out) {
    int idx = blockIdx.x * 256 + threadIdx.x;
    int c = (idx >> 5) & (CDIM - 1);
    float sc = g_scale[c], sh = g_shift[c];
    float4 o = ((const float4*)out)[idx];
    float4 v = ((const float4*)value)[idx];
    o.x = fmaxf(o.x * sc + sh, 0.f) + v.x;
    o.y = fmaxf(o.y * sc + sh, 0.f) + v.y;
    o.z = fmaxf(o.z * sc + sh, 0.f) + v.z;
    o.w = fmaxf(o.w * sc + sh, 0.f) + v.w;
    ((float4*)out)[idx] = o;
}

// ---------------- launch ----------------
extern "C" void kernel_launch(void* const* d_in, const int* in_sizes, int n_in,
                              void* d_out, int out_size) {
    const float* query = (const float*)d_in[0];
    const float* key   = (const float*)d_in[1];
    const float* value = (const float*)d_in[2];
    const float* Wq = (const float*)d_in[3];
    const float* bq = (const float*)d_in[4];
    const float* Wk = (const float*)d_in[5];
    const float* bk = (const float*)d_in[6];
    const float* Wv = (const float*)d_in[7];
    const float* bv = (const float*)d_in[8];
    const float* Wf = (const float*)d_in[9];
    const float* bf = (const float*)d_in[10];
    const float* gamma = (const float*)d_in[11];
    const float* beta  = (const float*)d_in[12];

    float* out = (float*)d_out;                               // [B,C,S]
    float* att = out + (size_t)BATCH * CDIM * SDIM;           // [B,C,C]

    dim3 blk(16, 16);
    prep_kernel<<<SDIM, SDIM>>>(Wq, bq, Wk, bk, Wv, bv, Wf, bf);
    proj_kernel<<<dim3(1, 512), blk>>>(query, 0);
    proj_kernel<<<dim3(1, 512), blk>>>(value, 1);
    keysplit_kernel<<<8192, 256>>>(key);
    scores_mma<<<dim3(4, 4, BATCH), 256>>>(att);
    softmax_kernel<<<8192, 256>>>(att);
    ctx_mma<<<dim3(4, BATCH), 256>>>(out);
    stats_kernel<<<1, CDIM>>>(gamma, beta);
    apply_kernel<<<8192, 256>>>(value, out);
}

// round 9
// speedup vs baseline: 2.8995x; 1.0366x over previous
#include <cuda_runtime.h>
#include <cuda_bf16.h>
#include <cstdint>

#define BATCH 128
#define CDIM 512
#define SDIM 128
#define MDIM 512
#define PAD 20    // ctx smem row stride (uint32)
#define APD 68    // scores A smem row stride (uint32), conflict-free
#define BPD 18    // scores B smem row stride (uint32), conflict-free

// ---------------- scratch (static device globals; no allocation) ----------------
__device__ __nv_bfloat16 g_xgh[BATCH * CDIM * SDIM];
__device__ __nv_bfloat16 g_xgl[BATCH * CDIM * SDIM];
__device__ __nv_bfloat16 g_vwfTh[BATCH * SDIM * CDIM]; // [b][s][c]
__device__ __nv_bfloat16 g_vwfTl[BATCH * SDIM * CDIM];
__device__ float g_gt[SDIM * SDIM];
__device__ float g_w[SDIM];
__device__ float g_weff[SDIM * SDIM];
__device__ float g_beff[SDIM];
__device__ float g_psum[CDIM * BATCH];
__device__ float g_psumsq[CDIM * BATCH];
__device__ float g_scale[CDIM];
__device__ float g_shift[CDIM];

// ---------------- helpers ----------------
__device__ __forceinline__ void split_bf16(float v, uint16_t& h, uint16_t& l) {
    __nv_bfloat16 hb = __float2bfloat16(v);
    h = *(uint16_t*)&hb;
    __nv_bfloat16 lb = __float2bfloat16(v - __bfloat162float(hb));
    l = *(uint16_t*)&lb;
}
// pack two floats into bf16x2 hi and lo words
__device__ __forceinline__ void split2(float a, float b, uint32_t& hw, uint32_t& lw) {
    uint16_t h0, l0, h1, l1;
    split_bf16(a, h0, l0);
    split_bf16(b, h1, l1);
    hw = (uint32_t)h0 | ((uint32_t)h1 << 16);
    lw = (uint32_t)l0 | ((uint32_t)l1 << 16);
}

// m16n8k16 bf16 MMA, fp32 accumulate (sm_80+; HMMA on sm_103a)
__device__ __forceinline__ void mma16816(float* c, const uint32_t* a, uint32_t b0, uint32_t b1) {
    asm volatile(
        "mma.sync.aligned.m16n8k16.row.col.f32.bf16.bf16.f32 "
        "{%0,%1,%2,%3}, {%4,%5,%6,%7}, {%8,%9}, {%0,%1,%2,%3};\n"
        : "+f"(c[0]), "+f"(c[1]), "+f"(c[2]), "+f"(c[3])
        : "r"(a[0]), "r"(a[1]), "r"(a[2]), "r"(a[3]), "r"(b0), "r"(b1));
}

// ---------------- K0: prep small matrices ----------------
__global__ void prep_kernel(const float* __restrict__ Wq, const float* __restrict__ bq,
                            const float* __restrict__ Wk, const float* __restrict__ bk,
                            const float* __restrict__ Wv, const float* __restrict__ bv,
                            const float* __restrict__ Wf, const float* __restrict__ bf) {
    const float SC = 0.04419417382415922f;   // 512^-0.5
    int n = blockIdx.x;
    int k = threadIdx.x;
    float g = 0.f, e = 0.f;
    for (int m = 0; m < MDIM; m++) {
        g += Wq[m * SDIM + k] * Wk[m * SDIM + n];
        e += Wf[n * MDIM + m] * Wv[m * SDIM + k];
    }
    g_gt[n * SDIM + k] = g * SC;
    g_weff[n * SDIM + k] = e;
    if (k == 0) {
        float w = 0.f, b = bf[n];
        for (int m = 0; m < MDIM; m++) {
            w += Wk[m * SDIM + n] * bq[m];
            b += Wf[n * MDIM + m] * bv[m];
        }
        g_w[n] = w * SC;
        g_beff[n] = b;
    }
}

// ---------------- K1: SIMT projection -> split-bf16 outputs ----------------
// sel 0: Xg = query*Gt^T + w  -> g_xgh/g_xgl  [b*c][s'] row-major
// sel 1: vwf = value*Weff^T + beff -> g_vwfTh/l TRANSPOSED [b][s][c]
__global__ __launch_bounds__(256, 2) void proj_kernel(const float* __restrict__ X, int sel) {
    __shared__ float Xs[32][132];
    __shared__ float Ws[32][132];
    const float* W = (sel == 0) ? g_gt : g_weff;
    const float* bias = (sel == 0) ? g_w : g_beff;

    int tx = threadIdx.x, ty = threadIdx.y;
    int tid = ty * 16 + tx;
    int row0 = blockIdx.y * 128;

    float acc[8][8];
    #pragma unroll
    for (int i = 0; i < 8; i++)
        #pragma unroll
        for (int j = 0; j < 8; j++) acc[i][j] = 0.f;

    for (int kc = 0; kc < 4; kc++) {
        __syncthreads();
        #pragma unroll
        for (int t = 0; t < 4; t++) {
            int f = tid + t * 256;
            int r = f >> 3;
            int k0 = (f & 7) * 4;
            float4 v = *(const float4*)(X + (size_t)(row0 + r) * SDIM + kc * 32 + k0);
            Xs[k0 + 0][r] = v.x; Xs[k0 + 1][r] = v.y; Xs[k0 + 2][r] = v.z; Xs[k0 + 3][r] = v.w;
            float4 w = *(const float4*)(W + (size_t)r * SDIM + kc * 32 + k0);
            Ws[k0 + 0][r] = w.x; Ws[k0 + 1][r] = w.y; Ws[k0 + 2][r] = w.z; Ws[k0 + 3][r] = w.w;
        }
        __syncthreads();
        #pragma unroll
        for (int k = 0; k < 32; k++) {
            float a[8], bb[8];
            *(float4*)(a)      = *(const float4*)&Xs[k][ty * 8];
            *(float4*)(a + 4)  = *(const float4*)&Xs[k][ty * 8 + 4];
            *(float4*)(bb)     = *(const float4*)&Ws[k][tx * 8];
            *(float4*)(bb + 4) = *(const float4*)&Ws[k][tx * 8 + 4];
            #pragma unroll
            for (int i = 0; i < 8; i++)
                #pragma unroll
                for (int j = 0; j < 8; j++) acc[i][j] += a[i] * bb[j];
        }
    }

    float bvv[8];
    #pragma unroll
    for (int j = 0; j < 8; j++) bvv[j] = bias[tx * 8 + j];
    #pragma unroll
    for (int i = 0; i < 8; i++)
        #pragma unroll
        for (int j = 0; j < 8; j++) acc[i][j] += bvv[j];

    if (sel == 0) {
        #pragma unroll
        for (int i = 0; i < 8; i++) {
            int row = row0 + ty * 8 + i;
            uint32_t hw[4], lw[4];
            #pragma unroll
            for (int q = 0; q < 4; q++)
                split2(acc[i][2 * q], acc[i][2 * q + 1], hw[q], lw[q]);
            *(uint4*)(g_xgh + (size_t)row * SDIM + tx * 8) = make_uint4(hw[0], hw[1], hw[2], hw[3]);
            *(uint4*)(g_xgl + (size_t)row * SDIM + tx * 8) = make_uint4(lw[0], lw[1], lw[2], lw[3]);
        }
    } else {
        int b = row0 >> 9;
        int c0 = (row0 & 511) + ty * 8;
        #pragma unroll
        for (int j = 0; j < 8; j++) {
            int s = tx * 8 + j;
            uint32_t hw[4], lw[4];
            #pragma unroll
            for (int q = 0; q < 4; q++)
                split2(acc[2 * q][j], acc[2 * q + 1][j], hw[q], lw[q]);
            size_t base = ((size_t)b * SDIM + s) * CDIM + c0;
            *(uint4*)(g_vwfTh + base) = make_uint4(hw[0], hw[1], hw[2], hw[3]);
            *(uint4*)(g_vwfTl + base) = make_uint4(lw[0], lw[1], lw[2], lw[3]);
        }
    }
}

// ---------------- K2: fused scores + softmax ----------------
// block: 32 q-rows x ALL 512 cols of one batch. 8 warps, warp tile 32x64.
// att[b, i0+r, :] = softmax_j( Xg[b,i0+r,:] . key[b,j,:] )
__global__ __launch_bounds__(256, 2) void scores_mma(const float* __restrict__ key,
                                                     float* __restrict__ att) {
    extern __shared__ uint32_t smem[];
    uint32_t* Ah = smem;                         // 32 x APD
    uint32_t* Al = Ah + 32 * APD;
    uint32_t* Bh = Al + 32 * APD;                // 512 x BPD (one 32-k chunk)
    uint32_t* Bl = Bh + 512 * BPD;
    float* red = (float*)(Bl + 512 * BPD);       // [32][8]

    int tid = threadIdx.x, lane = tid & 31, wn = tid >> 5;   // warp owns cols wn*64..+64
    int b = blockIdx.y, i0 = blockIdx.x * 32;

    // load A: 32 rows x 128 bf16 (64 u32) h/l
    #pragma unroll
    for (int t = 0; t < 2; t++) {
        int f = tid + t * 256;                   // 0..511
        int row = f >> 4, q = f & 15;
        size_t so = (size_t)(b * CDIM + i0 + row) * SDIM + q * 8;
        *(uint4*)&Ah[row * APD + q * 4] = *(const uint4*)(g_xgh + so);
        *(uint4*)&Al[row * APD + q * 4] = *(const uint4*)(g_xgl + so);
    }

    float acc[2][8][4];
    #pragma unroll
    for (int mt = 0; mt < 2; mt++)
        #pragma unroll
        for (int nt = 0; nt < 8; nt++)
            #pragma unroll
            for (int q = 0; q < 4; q++) acc[mt][nt][q] = 0.f;

    for (int kc = 0; kc < 4; kc++) {
        __syncthreads();
        // load B chunk: 512 key-rows x 32 fp32, split to bf16 h/l on the fly
        #pragma unroll
        for (int t = 0; t < 16; t++) {
            int f = tid + t * 256;               // 0..4095
            int row = f >> 3, q = f & 7;
            float4 v = *(const float4*)(key + (size_t)(b * CDIM + row) * SDIM + kc * 32 + q * 4);
            uint32_t h0, l0, h1, l1;
            split2(v.x, v.y, h0, l0);
            split2(v.z, v.w, h1, l1);
            Bh[row * BPD + q * 2] = h0; Bh[row * BPD + q * 2 + 1] = h1;
            Bl[row * BPD + q * 2] = l0; Bl[row * BPD + q * 2 + 1] = l1;
        }
        __syncthreads();
        #pragma unroll
        for (int ks = 0; ks < 2; ks++) {
            int ca = kc * 16 + ks * 8 + (lane & 3);
            uint32_t ah[2][4], al[2][4];
            #pragma unroll
            for (int mt = 0; mt < 2; mt++) {
                int r = (mt * 16 + (lane >> 2)) * APD;
                ah[mt][0] = Ah[r + ca];           ah[mt][1] = Ah[r + 8 * APD + ca];
                ah[mt][2] = Ah[r + ca + 4];       ah[mt][3] = Ah[r + 8 * APD + ca + 4];
                al[mt][0] = Al[r + ca];           al[mt][1] = Al[r + 8 * APD + ca];
                al[mt][2] = Al[r + ca + 4];       al[mt][3] = Al[r + 8 * APD + ca + 4];
            }
            int cb = ks * 8 + (lane & 3);
            #pragma unroll
            for (int nt = 0; nt < 8; nt++) {
                int n = (wn * 64 + nt * 8 + (lane >> 2)) * BPD;
                uint32_t bh0 = Bh[n + cb], bh1 = Bh[n + cb + 4];
                uint32_t bl0 = Bl[n + cb], bl1 = Bl[n + cb + 4];
                #pragma unroll
                for (int mt = 0; mt < 2; mt++) {
                    mma16816(acc[mt][nt], ah[mt], bh0, bh1);
                    mma16816(acc[mt][nt], ah[mt], bl0, bl1);
                    mma16816(acc[mt][nt], al[mt], bh0, bh1);
                }
            }
        }
    }

    // exp (no max-subtract: |logit| small; identical after normalization)
    #pragma unroll
    for (int mt = 0; mt < 2; mt++)
        #pragma unroll
        for (int nt = 0; nt < 8; nt++)
            #pragma unroll
            for (int q = 0; q < 4; q++) acc[mt][nt][q] = __expf(acc[mt][nt][q]);

    // per-warp row sums over its 64 cols
    #pragma unroll
    for (int mt = 0; mt < 2; mt++) {
        float s0 = 0.f, s8 = 0.f;
        #pragma unroll
        for (int nt = 0; nt < 8; nt++) {
            s0 += acc[mt][nt][0] + acc[mt][nt][1];
            s8 += acc[mt][nt][2] + acc[mt][nt][3];
        }
        #pragma unroll
        for (int off = 1; off <= 2; off <<= 1) {
            s0 += __shfl_xor_sync(0xffffffffu, s0, off);
            s8 += __shfl_xor_sync(0xffffffffu, s8, off);
        }
        if ((lane & 3) == 0) {
            int r = mt * 16 + (lane >> 2);
            red[r * 8 + wn] = s0;
            red[(r + 8) * 8 + wn] = s8;
        }
    }
    __syncthreads();

    // total row sums -> inverses; normalize + write final attention (fp32)
    #pragma unroll
    for (int mt = 0; mt < 2; mt++) {
        int r0 = mt * 16 + (lane >> 2);
        float t0 = 0.f, t8 = 0.f;
        #pragma unroll
        for (int w = 0; w < 8; w++) { t0 += red[r0 * 8 + w]; t8 += red[(r0 + 8) * 8 + w]; }
        float inv0 = 1.0f / t0, inv8 = 1.0f / t8;
        float* p0 = att + ((size_t)b * CDIM + i0 + r0) * CDIM;
        #pragma unroll
        for (int nt = 0; nt < 8; nt++) {
            int gcol = wn * 64 + nt * 8 + (lane & 3) * 2;
            *(float2*)(p0 + gcol) = make_float2(acc[mt][nt][0] * inv0, acc[mt][nt][1] * inv0);
            *(float2*)(p0 + 8 * CDIM + gcol) = make_float2(acc[mt][nt][2] * inv8, acc[mt][nt][3] * inv8);
        }
    }
}

// ---------------- K3: context GEMM (reads fp32 att, splits on load) + BN partials ----------------
// out[b, c0+128), s] = sum_j att[b,c,j] * vwfT[b,s,j];  K = 512
__global__ __launch_bounds__(256, 2) void ctx_mma(const float* __restrict__ att,
                                                  float* __restrict__ outp) {
    __shared__ uint32_t Ah[128 * PAD], Al[128 * PAD], Bh[128 * PAD], Bl[128 * PAD];
    __shared__ float redS[128][2], redQ[128][2];
    int tid = threadIdx.x, lane = tid & 31, wid = tid >> 5;
    int wm = wid & 3, wn = wid >> 2;
    int b = blockIdx.y, c0 = blockIdx.x * 128;

    const float* pA = att + ((size_t)b * CDIM + c0) * CDIM;
    const __nv_bfloat16* pBh = g_vwfTh + (size_t)b * SDIM * CDIM;
    const __nv_bfloat16* pBl = g_vwfTl + (size_t)b * SDIM * CDIM;

    float acc[2][8][4];
    #pragma unroll
    for (int mt = 0; mt < 2; mt++)
        #pragma unroll
        for (int nt = 0; nt < 8; nt++)
            #pragma unroll
            for (int q = 0; q < 4; q++) acc[mt][nt][q] = 0.f;

    for (int kc = 0; kc < 16; kc++) {
        __syncthreads();
        #pragma unroll
        for (int t2 = 0; t2 < 2; t2++) {
            int f = tid + t2 * 256;
            int row = f >> 2, q = f & 3;
            size_t so = (size_t)row * CDIM + kc * 32 + q * 8;
            // A: fp32 attention, split inline
            float4 v0 = *(const float4*)(pA + so);
            float4 v1 = *(const float4*)(pA + so + 4);
            uint32_t h0, l0, h1, l1, h2, l2, h3, l3;
            split2(v0.x, v0.y, h0, l0); split2(v0.z, v0.w, h1, l1);
            split2(v1.x, v1.y, h2, l2); split2(v1.z, v1.w, h3, l3);
            *(uint4*)&Ah[row * PAD + q * 4] = make_uint4(h0, h1, h2, h3);
            *(uint4*)&Al[row * PAD + q * 4] = make_uint4(l0, l1, l2, l3);
            // B: pre-split bf16
            *(uint4*)&Bh[row * PAD + q * 4] = *(const uint4*)(pBh + so);
            *(uint4*)&Bl[row * PAD + q * 4] = *(const uint4*)(pBl + so);
        }
        __syncthreads();
        #pragma unroll
        for (int ks = 0; ks < 2; ks++) {
            int cb = ks * 8 + (lane & 3);
            uint32_t ah[2][4], al[2][4];
            #pragma unroll
            for (int mt = 0; mt < 2; mt++) {
                int r = (wm * 32 + mt * 16 + (lane >> 2)) * PAD;
                ah[mt][0] = Ah[r + cb];           ah[mt][1] = Ah[r + 8 * PAD + cb];
                ah[mt][2] = Ah[r + cb + 4];       ah[mt][3] = Ah[r + 8 * PAD + cb + 4];
                al[mt][0] = Al[r + cb];           al[mt][1] = Al[r + 8 * PAD + cb];
                al[mt][2] = Al[r + cb + 4];       al[mt][3] = Al[r + 8 * PAD + cb + 4];
            }
            #pragma unroll
            for (int nt = 0; nt < 8; nt++) {
                int n = (wn * 64 + nt * 8 + (lane >> 2)) * PAD;
                uint32_t bh0 = Bh[n + cb], bh1 = Bh[n + cb + 4];
                uint32_t bl0 = Bl[n + cb], bl1 = Bl[n + cb + 4];
                #pragma unroll
                for (int mt = 0; mt < 2; mt++) {
                    mma16816(acc[mt][nt], ah[mt], bh0, bh1);
                    mma16816(acc[mt][nt], ah[mt], bl0, bl1);
                    mma16816(acc[mt][nt], al[mt], bh0, bh1);
                }
            }
        }
    }

    // write output + per-row BN partial sums
    #pragma unroll
    for (int mt = 0; mt < 2; mt++) {
        int grow = c0 + wm * 32 + mt * 16 + (lane >> 2);
        float sA = 0.f, qA = 0.f, sB = 0.f, qB = 0.f;
        #pragma unroll
        for (int nt = 0; nt < 8; nt++) {
            int gcol = wn * 64 + nt * 8 + (lane & 3) * 2;
            float* p = outp + ((size_t)b * CDIM + grow) * SDIM + gcol;
            float v0 = acc[mt][nt][0], v1 = acc[mt][nt][1];
            float v2 = acc[mt][nt][2], v3 = acc[mt][nt][3];
            *(float2*)p = make_float2(v0, v1);
            *(float2*)(p + 8 * SDIM) = make_float2(v2, v3);
            sA += v0 + v1; qA += v0 * v0 + v1 * v1;
            sB += v2 + v3; qB += v2 * v2 + v3 * v3;
        }
        #pragma unroll
        for (int off = 1; off <= 2; off <<= 1) {
            sA += __shfl_xor_sync(0xffffffffu, sA, off);
            qA += __shfl_xor_sync(0xffffffffu, qA, off);
            sB += __shfl_xor_sync(0xffffffffu, sB, off);
            qB += __shfl_xor_sync(0xffffffffu, qB, off);
        }
        if ((lane & 3) == 0) {
            int lr = wm * 32 + mt * 16 + (lane >> 2);
            redS[lr][wn] = sA;     redQ[lr][wn] = qA;
            redS[lr + 8][wn] = sB; redQ[lr + 8][wn] = qB;
        }
    }
    __syncthreads();
    if (tid < 128) {
        int c = c0 + tid;
        g_psum[(size_t)c * BATCH + b] = redS[tid][0] + redS[tid][1];
        g_psumsq[(size_t)c * BATCH + b] = redQ[tid][0] + redQ[tid][1];
    }
}

// ---------------- K4: finalize BN stats ----------------
__global__ void stats_kernel(const float* __restrict__ gamma, const float* __restrict__ beta) {
    int c = threadIdx.x;
    float s = 0.f, ss = 0.f;
    for (int b = 0; b < BATCH; b++) {
        s += g_psum[(size_t)c * BATCH + b];
        ss += g_psumsq[(size_t)c * BATCH + b];
    }
    const float inv_n = 1.0f / (float)(BATCH * SDIM);
    float mean = s * inv_n;
    float var = ss * inv_n - mean * mean;
    float sc = gamma[c] * rsqrtf(var + 1e-5f);
    g_scale[c] = sc;
    g_shift[c] = beta[c] - mean * sc;
}

// ---------------- K5: apply BN + relu + residual ----------------
__global__ void apply_kernel(const float* __restrict__ value, float* __restrict__ out) {
    int idx = blockIdx.x * 256 + threadIdx.x;
    int c = (idx >> 5) & (CDIM - 1);
    float sc = g_scale[c], sh = g_shift[c];
    float4 o = ((const float4*)out)[idx];
    float4 v = ((const float4*)value)[idx];
    o.x = fmaxf(o.x * sc + sh, 0.f) + v.x;
    o.y = fmaxf(o.y * sc + sh, 0.f) + v.y;
    o.z = fmaxf(o.z * sc + sh, 0.f) + v.z;
    o.w = fmaxf(o.w * sc + sh, 0.f) + v.w;
    ((float4*)out)[idx] = o;
}

// ---------------- launch ----------------
extern "C" void kernel_launch(void* const* d_in, const int* in_sizes, int n_in,
                              void* d_out, int out_size) {
    const float* query = (const float*)d_in[0];
    const float* key   = (const float*)d_in[1];
    const float* value = (const float*)d_in[2];
    const float* Wq = (const float*)d_in[3];
    const float* bq = (const float*)d_in[4];
    const float* Wk = (const float*)d_in[5];
    const float* bk = (const float*)d_in[6];
    const float* Wv = (const float*)d_in[7];
    const float* bv = (const float*)d_in[8];
    const float* Wf = (const float*)d_in[9];
    const float* bf = (const float*)d_in[10];
    const float* gamma = (const float*)d_in[11];
    const float* beta  = (const float*)d_in[12];

    float* out = (float*)d_out;                               // [B,C,S]
    float* att = out + (size_t)BATCH * CDIM * SDIM;           // [B,C,C]

    // scores dynamic smem: A h/l (2*32*APD) + B h/l (2*512*BPD) + red (32*8 floats)
    int scores_smem = (2 * 32 * APD + 2 * 512 * BPD + 32 * 8) * 4;
    cudaFuncSetAttribute(scores_mma, cudaFuncAttributeMaxDynamicSharedMemorySize, scores_smem);

    dim3 blk(16, 16);
    prep_kernel<<<SDIM, SDIM>>>(Wq, bq, Wk, bk, Wv, bv, Wf, bf);
    proj_kernel<<<dim3(1, 512), blk>>>(query, 0);
    proj_kernel<<<dim3(1, 512), blk>>>(value, 1);
    scores_mma<<<dim3(16, BATCH), 256, scores_smem>>>(key, att);
    ctx_mma<<<dim3(4, BATCH), 256>>>(att, out);
    stats_kernel<<<1, CDIM>>>(gamma, beta);
    apply_kernel<<<8192, 256>>>(value, out);
}

// round 11
// speedup vs baseline: 2.9240x; 1.0085x over previous
#include <cuda_runtime.h>
#include <cuda_bf16.h>
#include <cstdint>

#define BATCH 128
#define CDIM 512
#define SDIM 128
#define MDIM 512
#define PAD 20    // ctx/scores-B smem row stride (u32); 80B: 16B-aligned, conflict-free
#define APD 68    // scores A smem row stride (u32); 272B: 16B-aligned, conflict-free

// ---------------- scratch (static device globals; no allocation) ----------------
__device__ __nv_bfloat16 g_xgh[BATCH * CDIM * SDIM];
__device__ __nv_bfloat16 g_xgl[BATCH * CDIM * SDIM];
__device__ __nv_bfloat16 g_keyh[BATCH * CDIM * SDIM];
__device__ __nv_bfloat16 g_keyl[BATCH * CDIM * SDIM];
__device__ __nv_bfloat16 g_vwfTh[BATCH * SDIM * CDIM]; // [b][s][c]
__device__ __nv_bfloat16 g_vwfTl[BATCH * SDIM * CDIM];
__device__ float g_gt[SDIM * SDIM];
__device__ float g_w[SDIM];
__device__ float g_weff[SDIM * SDIM];
__device__ float g_beff[SDIM];
__device__ float g_psum[CDIM * BATCH];
__device__ float g_psumsq[CDIM * BATCH];
__device__ float g_scale[CDIM];
__device__ float g_shift[CDIM];

// ---------------- helpers ----------------
__device__ __forceinline__ void split_bf16(float v, uint16_t& h, uint16_t& l) {
    __nv_bfloat16 hb = __float2bfloat16(v);
    h = *(uint16_t*)&hb;
    __nv_bfloat16 lb = __float2bfloat16(v - __bfloat162float(hb));
    l = *(uint16_t*)&lb;
}
__device__ __forceinline__ void split2(float a, float b, uint32_t& hw, uint32_t& lw) {
    uint16_t h0, l0, h1, l1;
    split_bf16(a, h0, l0);
    split_bf16(b, h1, l1);
    hw = (uint32_t)h0 | ((uint32_t)h1 << 16);
    lw = (uint32_t)l0 | ((uint32_t)l1 << 16);
}

// m16n8k16 bf16 MMA, fp32 accumulate (sm_80+; HMMA on sm_103a)
__device__ __forceinline__ void mma16816(float* c, const uint32_t* a, uint32_t b0, uint32_t b1) {
    asm volatile(
        "mma.sync.aligned.m16n8k16.row.col.f32.bf16.bf16.f32 "
        "{%0,%1,%2,%3}, {%4,%5,%6,%7}, {%8,%9}, {%0,%1,%2,%3};\n"
        : "+f"(c[0]), "+f"(c[1]), "+f"(c[2]), "+f"(c[3])
        : "r"(a[0]), "r"(a[1]), "r"(a[2]), "r"(a[3]), "r"(b0), "r"(b1));
}
__device__ __forceinline__ void ldmx4(uint32_t* r, uint32_t addr) {
    asm volatile("ldmatrix.sync.aligned.m8n8.x4.shared.b16 {%0,%1,%2,%3}, [%4];"
        : "=r"(r[0]), "=r"(r[1]), "=r"(r[2]), "=r"(r[3]) : "r"(addr));
}
__device__ __forceinline__ uint32_t sptr(const void* p) {
    return (uint32_t)__cvta_generic_to_shared(p);
}

// ---------------- K0: prep small matrices ----------------
__global__ void prep_kernel(const float* __restrict__ Wq, const float* __restrict__ bq,
                            const float* __restrict__ Wk, const float* __restrict__ bk,
                            const float* __restrict__ Wv, const float* __restrict__ bv,
                            const float* __restrict__ Wf, const float* __restrict__ bf) {
    const float SC = 0.04419417382415922f;   // 512^-0.5
    int n = blockIdx.x;
    int k = threadIdx.x;
    float g = 0.f, e = 0.f;
    for (int m = 0; m < MDIM; m++) {
        g += Wq[m * SDIM + k] * Wk[m * SDIM + n];
        e += Wf[n * MDIM + m] * Wv[m * SDIM + k];
    }
    g_gt[n * SDIM + k] = g * SC;
    g_weff[n * SDIM + k] = e;
    if (k == 0) {
        float w = 0.f, b = bf[n];
        for (int m = 0; m < MDIM; m++) {
            w += Wk[m * SDIM + n] * bq[m];
            b += Wf[n * MDIM + m] * bv[m];
        }
        g_w[n] = w * SC;
        g_beff[n] = b;
    }
}

// ---------------- K1: SIMT projection -> split-bf16 outputs ----------------
__global__ __launch_bounds__(256, 2) void proj_kernel(const float* __restrict__ X, int sel) {
    __shared__ float Xs[32][132];
    __shared__ float Ws[32][132];
    const float* W = (sel == 0) ? g_gt : g_weff;
    const float* bias = (sel == 0) ? g_w : g_beff;

    int tx = threadIdx.x, ty = threadIdx.y;
    int tid = ty * 16 + tx;
    int row0 = blockIdx.y * 128;

    float acc[8][8];
    #pragma unroll
    for (int i = 0; i < 8; i++)
        #pragma unroll
        for (int j = 0; j < 8; j++) acc[i][j] = 0.f;

    for (int kc = 0; kc < 4; kc++) {
        __syncthreads();
        #pragma unroll
        for (int t = 0; t < 4; t++) {
            int f = tid + t * 256;
            int r = f >> 3;
            int k0 = (f & 7) * 4;
            float4 v = *(const float4*)(X + (size_t)(row0 + r) * SDIM + kc * 32 + k0);
            Xs[k0 + 0][r] = v.x; Xs[k0 + 1][r] = v.y; Xs[k0 + 2][r] = v.z; Xs[k0 + 3][r] = v.w;
            float4 w = *(const float4*)(W + (size_t)r * SDIM + kc * 32 + k0);
            Ws[k0 + 0][r] = w.x; Ws[k0 + 1][r] = w.y; Ws[k0 + 2][r] = w.z; Ws[k0 + 3][r] = w.w;
        }
        __syncthreads();
        #pragma unroll
        for (int k = 0; k < 32; k++) {
            float a[8], bb[8];
            *(float4*)(a)      = *(const float4*)&Xs[k][ty * 8];
            *(float4*)(a + 4)  = *(const float4*)&Xs[k][ty * 8 + 4];
            *(float4*)(bb)     = *(const float4*)&Ws[k][tx * 8];
            *(float4*)(bb + 4) = *(const float4*)&Ws[k][tx * 8 + 4];
            #pragma unroll
            for (int i = 0; i < 8; i++)
                #pragma unroll
                for (int j = 0; j < 8; j++) acc[i][j] += a[i] * bb[j];
        }
    }

    float bvv[8];
    #pragma unroll
    for (int j = 0; j < 8; j++) bvv[j] = bias[tx * 8 + j];
    #pragma unroll
    for (int i = 0; i < 8; i++)
        #pragma unroll
        for (int j = 0; j < 8; j++) acc[i][j] += bvv[j];

    if (sel == 0) {
        #pragma unroll
        for (int i = 0; i < 8; i++) {
            int row = row0 + ty * 8 + i;
            uint32_t hw[4], lw[4];
            #pragma unroll
            for (int q = 0; q < 4; q++)
                split2(acc[i][2 * q], acc[i][2 * q + 1], hw[q], lw[q]);
            *(uint4*)(g_xgh + (size_t)row * SDIM + tx * 8) = make_uint4(hw[0], hw[1], hw[2], hw[3]);
            *(uint4*)(g_xgl + (size_t)row * SDIM + tx * 8) = make_uint4(lw[0], lw[1], lw[2], lw[3]);
        }
    } else {
        int b = row0 >> 9;
        int c0 = (row0 & 511) + ty * 8;
        #pragma unroll
        for (int j = 0; j < 8; j++) {
            int s = tx * 8 + j;
            uint32_t hw[4], lw[4];
            #pragma unroll
            for (int q = 0; q < 4; q++)
                split2(acc[2 * q][j], acc[2 * q + 1][j], hw[q], lw[q]);
            size_t base = ((size_t)b * SDIM + s) * CDIM + c0;
            *(uint4*)(g_vwfTh + base) = make_uint4(hw[0], hw[1], hw[2], hw[3]);
            *(uint4*)(g_vwfTl + base) = make_uint4(lw[0], lw[1], lw[2], lw[3]);
        }
    }
}

// ---------------- K2: split key into bf16 hi/lo ----------------
__global__ void keysplit_kernel(const float* __restrict__ key) {
    int idx = blockIdx.x * 256 + threadIdx.x;
    float4 v = ((const float4*)key)[idx];
    uint32_t h0, l0, h1, l1;
    split2(v.x, v.y, h0, l0);
    split2(v.z, v.w, h1, l1);
    ((uint2*)g_keyh)[idx] = make_uint2(h0, h1);
    ((uint2*)g_keyl)[idx] = make_uint2(l0, l1);
}

// ---------------- K3: fused scores + softmax (ldmatrix feed) ----------------
// block: 32 q-rows x ALL 512 cols of one batch. 8 warps, warp tile 32x64.
__global__ __launch_bounds__(256, 2) void scores_mma(float* __restrict__ att) {
    extern __shared__ uint32_t smem[];
    uint32_t* Ah = smem;                         // 32 x APD
    uint32_t* Al = Ah + 32 * APD;
    uint32_t* Bh = Al + 32 * APD;                // 512 x PAD (one 32-k chunk)
    uint32_t* Bl = Bh + 512 * PAD;
    float* red = (float*)(Bl + 512 * PAD);       // [32][8]

    int tid = threadIdx.x, lane = tid & 31, wn = tid >> 5;
    int b = blockIdx.y, i0 = blockIdx.x * 32;

    uint32_t ahb = sptr(Ah), alb = sptr(Al), bhb = sptr(Bh), blb = sptr(Bl);

    // load A: 32 rows x 128 bf16 = 16 uint4 per row, h and l
    #pragma unroll
    for (int t = 0; t < 2; t++) {
        int f = tid + t * 256;                   // 0..511
        int row = f >> 4, q = f & 15;
        size_t so = (size_t)(b * CDIM + i0 + row) * SDIM + q * 8;
        *(uint4*)&Ah[row * APD + q * 4] = *(const uint4*)(g_xgh + so);
        *(uint4*)&Al[row * APD + q * 4] = *(const uint4*)(g_xgl + so);
    }

    float acc[2][8][4];
    #pragma unroll
    for (int mt = 0; mt < 2; mt++)
        #pragma unroll
        for (int nt = 0; nt < 8; nt++)
            #pragma unroll
            for (int q = 0; q < 4; q++) acc[mt][nt][q] = 0.f;

    // ldmatrix lane-address components
    uint32_t a_row = ((lane >> 3) & 1) * 8 + (lane & 7);
    uint32_t a_koff = (lane >> 4) * 16;                 // bytes
    uint32_t b_nrow = ((lane >> 4) & 1) * 8 + (lane & 7);
    uint32_t b_koff = ((lane >> 3) & 1) * 16;           // bytes

    for (int kc = 0; kc < 4; kc++) {
        __syncthreads();
        // load B chunk: 512 rows x 32 bf16 (4 uint4) h and l, pre-split
        #pragma unroll
        for (int t = 0; t < 8; t++) {
            int f = tid + t * 256;                      // 0..2047
            int row = f >> 2, q = f & 3;
            size_t so = (size_t)(b * CDIM + row) * SDIM + kc * 32 + q * 8;
            *(uint4*)&Bh[row * PAD + q * 4] = *(const uint4*)(g_keyh + so);
            *(uint4*)&Bl[row * PAD + q * 4] = *(const uint4*)(g_keyl + so);
        }
        __syncthreads();
        #pragma unroll
        for (int ks = 0; ks < 2; ks++) {
            uint32_t kbA = (uint32_t)(kc * 32 + ks * 16) * 2 + a_koff;   // bytes
            uint32_t kbB = (uint32_t)(ks * 16) * 2 + b_koff;
            uint32_t ah[2][4], al[2][4];
            #pragma unroll
            for (int mt = 0; mt < 2; mt++) {
                uint32_t ro = (mt * 16 + a_row) * (APD * 4);
                ldmx4(ah[mt], ahb + ro + kbA);
                ldmx4(al[mt], alb + ro + kbA);
            }
            #pragma unroll
            for (int np = 0; np < 4; np++) {
                uint32_t no = (wn * 64 + np * 16 + b_nrow) * (PAD * 4);
                uint32_t bh[4], bl[4];
                ldmx4(bh, bhb + no + kbB);    // {b0_ntA, b1_ntA, b0_ntB, b1_ntB}
                ldmx4(bl, blb + no + kbB);
                #pragma unroll
                for (int half = 0; half < 2; half++) {
                    int nt = np * 2 + half;
                    uint32_t h0 = bh[half * 2], h1 = bh[half * 2 + 1];
                    uint32_t l0 = bl[half * 2], l1 = bl[half * 2 + 1];
                    #pragma unroll
                    for (int mt = 0; mt < 2; mt++) {
                        mma16816(acc[mt][nt], ah[mt], h0, h1);
                        mma16816(acc[mt][nt], ah[mt], l0, l1);
                        mma16816(acc[mt][nt], al[mt], h0, h1);
                    }
                }
            }
        }
    }

    // exp (no max-subtract: |logit| small; identical after normalization)
    #pragma unroll
    for (int mt = 0; mt < 2; mt++)
        #pragma unroll
        for (int nt = 0; nt < 8; nt++)
            #pragma unroll
            for (int q = 0; q < 4; q++) acc[mt][nt][q] = __expf(acc[mt][nt][q]);

    // per-warp row sums over its 64 cols
    #pragma unroll
    for (int mt = 0; mt < 2; mt++) {
        float s0 = 0.f, s8 = 0.f;
        #pragma unroll
        for (int nt = 0; nt < 8; nt++) {
            s0 += acc[mt][nt][0] + acc[mt][nt][1];
            s8 += acc[mt][nt][2] + acc[mt][nt][3];
        }
        #pragma unroll
        for (int off = 1; off <= 2; off <<= 1) {
            s0 += __shfl_xor_sync(0xffffffffu, s0, off);
            s8 += __shfl_xor_sync(0xffffffffu, s8, off);
        }
        if ((lane & 3) == 0) {
            int r = mt * 16 + (lane >> 2);
            red[r * 8 + wn] = s0;
            red[(r + 8) * 8 + wn] = s8;
        }
    }
    __syncthreads();

    // total row sums -> normalize + write final attention (fp32)
    #pragma unroll
    for (int mt = 0; mt < 2; mt++) {
        int r0 = mt * 16 + (lane >> 2);
        float t0 = 0.f, t8 = 0.f;
        #pragma unroll
        for (int w = 0; w < 8; w++) { t0 += red[r0 * 8 + w]; t8 += red[(r0 + 8) * 8 + w]; }
        float inv0 = 1.0f / t0, inv8 = 1.0f / t8;
        float* p0 = att + ((size_t)b * CDIM + i0 + r0) * CDIM;
        #pragma unroll
        for (int nt = 0; nt < 8; nt++) {
            int gcol = wn * 64 + nt * 8 + (lane & 3) * 2;
            *(float2*)(p0 + gcol) = make_float2(acc[mt][nt][0] * inv0, acc[mt][nt][1] * inv0);
            *(float2*)(p0 + 8 * CDIM + gcol) = make_float2(acc[mt][nt][2] * inv8, acc[mt][nt][3] * inv8);
        }
    }
}

// ---------------- K4: context GEMM (ldmatrix feed) + BN partials ----------------
// out[b, c0+128), s] = sum_j att[b,c,j] * vwfT[b,s,j];  K = 512
__global__ __launch_bounds__(256, 2) void ctx_mma(const float* __restrict__ att,
                                                  float* __restrict__ outp) {
    __shared__ __align__(16) uint32_t Ah[128 * PAD], Al[128 * PAD], Bh[128 * PAD], Bl[128 * PAD];
    __shared__ float redS[128][2], redQ[128][2];
    int tid = threadIdx.x, lane = tid & 31, wid = tid >> 5;
    int wm = wid & 3, wn = wid >> 2;
    int b = blockIdx.y, c0 = blockIdx.x * 128;

    const float* pA = att + ((size_t)b * CDIM + c0) * CDIM;
    const __nv_bfloat16* pBh = g_vwfTh + (size_t)b * SDIM * CDIM;
    const __nv_bfloat16* pBl = g_vwfTl + (size_t)b * SDIM * CDIM;

    uint32_t ahb = sptr(Ah), alb = sptr(Al), bhb = sptr(Bh), blb = sptr(Bl);

    float acc[2][8][4];
    #pragma unroll
    for (int mt = 0; mt < 2; mt++)
        #pragma unroll
        for (int nt = 0; nt < 8; nt++)
            #pragma unroll
            for (int q = 0; q < 4; q++) acc[mt][nt][q] = 0.f;

    uint32_t a_row = ((lane >> 3) & 1) * 8 + (lane & 7);
    uint32_t a_koff = (lane >> 4) * 16;
    uint32_t b_nrow = ((lane >> 4) & 1) * 8 + (lane & 7);
    uint32_t b_koff = ((lane >> 3) & 1) * 16;

    for (int kc = 0; kc < 16; kc++) {
        __syncthreads();
        #pragma unroll
        for (int t2 = 0; t2 < 2; t2++) {
            int f = tid + t2 * 256;
            int row = f >> 2, q = f & 3;
            size_t so = (size_t)row * CDIM + kc * 32 + q * 8;
            // A: fp32 attention, split inline
            float4 v0 = *(const float4*)(pA + so);
            float4 v1 = *(const float4*)(pA + so + 4);
            uint32_t h0, l0, h1, l1, h2, l2, h3, l3;
            split2(v0.x, v0.y, h0, l0); split2(v0.z, v0.w, h1, l1);
            split2(v1.x, v1.y, h2, l2); split2(v1.z, v1.w, h3, l3);
            *(uint4*)&Ah[row * PAD + q * 4] = make_uint4(h0, h1, h2, h3);
            *(uint4*)&Al[row * PAD + q * 4] = make_uint4(l0, l1, l2, l3);
            // B: pre-split bf16
            *(uint4*)&Bh[row * PAD + q * 4] = *(const uint4*)(pBh + so);
            *(uint4*)&Bl[row * PAD + q * 4] = *(const uint4*)(pBl + so);
        }
        __syncthreads();
        #pragma unroll
        for (int ks = 0; ks < 2; ks++) {
            uint32_t kb = (uint32_t)(ks * 16) * 2;
            uint32_t ah[2][4], al[2][4];
            #pragma unroll
            for (int mt = 0; mt < 2; mt++) {
                uint32_t ro = (wm * 32 + mt * 16 + a_row) * (PAD * 4);
                ldmx4(ah[mt], ahb + ro + kb + a_koff);
                ldmx4(al[mt], alb + ro + kb + a_koff);
            }
            #pragma unroll
            for (int np = 0; np < 4; np++) {
                uint32_t no = (wn * 64 + np * 16 + b_nrow) * (PAD * 4);
                uint32_t bh[4], bl[4];
                ldmx4(bh, bhb + no + kb + b_koff);
                ldmx4(bl, blb + no + kb + b_koff);
                #pragma unroll
                for (int half = 0; half < 2; half++) {
                    int nt = np * 2 + half;
                    uint32_t h0 = bh[half * 2], h1 = bh[half * 2 + 1];
                    uint32_t l0 = bl[half * 2], l1 = bl[half * 2 + 1];
                    #pragma unroll
                    for (int mt = 0; mt < 2; mt++) {
                        mma16816(acc[mt][nt], ah[mt], h0, h1);
                        mma16816(acc[mt][nt], ah[mt], l0, l1);
                        mma16816(acc[mt][nt], al[mt], h0, h1);
                    }
                }
            }
        }
    }

    // write output + per-row BN partial sums
    #pragma unroll
    for (int mt = 0; mt < 2; mt++) {
        int grow = c0 + wm * 32 + mt * 16 + (lane >> 2);
        float sA = 0.f, qA = 0.f, sB = 0.f, qB = 0.f;
        #pragma unroll
        for (int nt = 0; nt < 8; nt++) {
            int gcol = wn * 64 + nt * 8 + (lane & 3) * 2;
            float* p = outp + ((size_t)b * CDIM + grow) * SDIM + gcol;
            float v0 = acc[mt][nt][0], v1 = acc[mt][nt][1];
            float v2 = acc[mt][nt][2], v3 = acc[mt][nt][3];
            *(float2*)p = make_float2(v0, v1);
            *(float2*)(p + 8 * SDIM) = make_float2(v2, v3);
            sA += v0 + v1; qA += v0 * v0 + v1 * v1;
            sB += v2 + v3; qB += v2 * v2 + v3 * v3;
        }
        #pragma unroll
        for (int off = 1; off <= 2; off <<= 1) {
            sA += __shfl_xor_sync(0xffffffffu, sA, off);
            qA += __shfl_xor_sync(0xffffffffu, qA, off);
            sB += __shfl_xor_sync(0xffffffffu, sB, off);
            qB += __shfl_xor_sync(0xffffffffu, qB, off);
        }
        if ((lane & 3) == 0) {
            int lr = wm * 32 + mt * 16 + (lane >> 2);
            redS[lr][wn] = sA;     redQ[lr][wn] = qA;
            redS[lr + 8][wn] = sB; redQ[lr + 8][wn] = qB;
        }
    }
    __syncthreads();
    if (tid < 128) {
        int c = c0 + tid;
        g_psum[(size_t)c * BATCH + b] = redS[tid][0] + redS[tid][1];
        g_psumsq[(size_t)c * BATCH + b] = redQ[tid][0] + redQ[tid][1];
    }
}

// ---------------- K5: finalize BN stats ----------------
__global__ void stats_kernel(const float* __restrict__ gamma, const float* __restrict__ beta) {
    int c = threadIdx.x;
    float s = 0.f, ss = 0.f;
    for (int b = 0; b < BATCH; b++) {
        s += g_psum[(size_t)c * BATCH + b];
        ss += g_psumsq[(size_t)c * BATCH + b];
    }
    const float inv_n = 1.0f / (float)(BATCH * SDIM);
    float mean = s * inv_n;
    float var = ss * inv_n - mean * mean;
    float sc = gamma[c] * rsqrtf(var + 1e-5f);
    g_scale[c] = sc;
    g_shift[c] = beta[c] - mean * sc;
}

// ---------------- K6: apply BN + relu + residual ----------------
__global__ void apply_kernel(const float* __restrict__ value, float* __restrict__ out) {
    int idx = blockIdx.x * 256 + threadIdx.x;
    int c = (idx >> 5) & (CDIM - 1);
    float sc = g_scale[c], sh = g_shift[c];
    float4 o = ((const float4*)out)[idx];
    float4 v = ((const float4*)value)[idx];
    o.x = fmaxf(o.x * sc + sh, 0.f) + v.x;
    o.y = fmaxf(o.y * sc + sh, 0.f) + v.y;
    o.z = fmaxf(o.z * sc + sh, 0.f) + v.z;
    o.w = fmaxf(o.w * sc + sh, 0.f) + v.w;
    ((float4*)out)[idx] = o;
}

// ---------------- launch ----------------
extern "C" void kernel_launch(void* const* d_in, const int* in_sizes, int n_in,
                              void* d_out, int out_size) {
    const float* query = (const float*)d_in[0];
    const float* key   = (const float*)d_in[1];
    const float* value = (const float*)d_in[2];
    const float* Wq = (const float*)d_in[3];
    const float* bq = (const float*)d_in[4];
    const float* Wk = (const float*)d_in[5];
    const float* bk = (const float*)d_in[6];
    const float* Wv = (const float*)d_in[7];
    const float* bv = (const float*)d_in[8];
    const float* Wf = (const float*)d_in[9];
    const float* bf = (const float*)d_in[10];
    const float* gamma = (const float*)d_in[11];
    const float* beta  = (const float*)d_in[12];

    float* out = (float*)d_out;                               // [B,C,S]
    float* att = out + (size_t)BATCH * CDIM * SDIM;           // [B,C,C]

    // scores dynamic smem: A h/l (2*32*APD) + B h/l (2*512*PAD) + red (32*8)
    int scores_smem = (2 * 32 * APD + 2 * 512 * PAD + 32 * 8) * 4;
    cudaFuncSetAttribute(scores_mma, cudaFuncAttributeMaxDynamicSharedMemorySize, scores_smem);

    dim3 blk(16, 16);
    prep_kernel<<<SDIM, SDIM>>>(Wq, bq, Wk, bk, Wv, bv, Wf, bf);
    proj_kernel<<<dim3(1, 512), blk>>>(query, 0);
    proj_kernel<<<dim3(1, 512), blk>>>(value, 1);
    keysplit_kernel<<<8192, 256>>>(key);
    scores_mma<<<dim3(16, BATCH), 256, scores_smem>>>(att);
    ctx_mma<<<dim3(4, BATCH), 256>>>(att, out);
    stats_kernel<<<1, CDIM>>>(gamma, beta);
    apply_kernel<<<8192, 256>>>(value, out);
}